// round 1
// baseline (speedup 1.0000x reference)
#include <cuda_runtime.h>
#include <math.h>

#define DIMS 1024
#define KSZ  128
#define SEQ  2048
#define BATCH 8
#define M_TOTAL (BATCH*SEQ)     // 16384
#define OUTD (DIMS + KSZ)       // 1152

// scratch (allocation-free rule: __device__ globals)
__device__ float g_keys[M_TOTAL * KSZ];
__device__ float g_vals[M_TOTAL * KSZ];

__device__ __forceinline__ unsigned f2tf(float x) {
    unsigned r; asm("cvt.rna.tf32.f32 %0, %1;" : "=r"(r) : "f"(x)); return r;
}

__device__ __forceinline__ void mma_tf32(float* c,
        unsigned a0, unsigned a1, unsigned a2, unsigned a3,
        unsigned b0, unsigned b1) {
    asm volatile(
        "mma.sync.aligned.m16n8k8.row.col.f32.tf32.tf32.f32 "
        "{%0,%1,%2,%3}, {%4,%5,%6,%7}, {%8,%9}, {%0,%1,%2,%3};"
        : "+f"(c[0]), "+f"(c[1]), "+f"(c[2]), "+f"(c[3])
        : "r"(a0), "r"(a1), "r"(a2), "r"(a3), "r"(b0), "r"(b1));
}

// ---------------------------------------------------------------------------
// Kernel 1: copy minibatch into out[:, 0:1024]
// ---------------------------------------------------------------------------
__global__ void copy_x_kernel(const float* __restrict__ X, float* __restrict__ out) {
    int row = blockIdx.x;
    int c = threadIdx.x * 4;
    float4 v = *(const float4*)(X + (size_t)row * DIMS + c);
    *(float4*)(out + (size_t)row * OUTD + c) = v;
}

// ---------------------------------------------------------------------------
// Kernel 2: KV projection GEMM (tf32 mma), writes g_keys / g_vals
// M=16384, N=256 (cols 0..127 -> Wk, 128..255 -> Wv), Kd=1024
// BM=128, BN=64, BK=32, 256 threads, warp grid 4x2 (warp tile 32x32)
// ---------------------------------------------------------------------------
#define GBM 128
#define GBN 64
#define GBK 32
#define GLDA 36
#define GLDB 36

__global__ __launch_bounds__(256) void kv_gemm_kernel(
        const float* __restrict__ X,
        const float* __restrict__ Wk, const float* __restrict__ bk,
        const float* __restrict__ Wv, const float* __restrict__ bv) {
    __shared__ unsigned As[GBM * GLDA];   // [m][k], tf32 bits
    __shared__ unsigned Bs[GBN * GLDB];   // [n][k], tf32 bits

    const int tid = threadIdx.x, lane = tid & 31, wid = tid >> 5;
    const int wm = wid & 3, wn = wid >> 2;
    const int m0 = blockIdx.x * GBM;
    const int n0 = blockIdx.y * GBN;

    const float* W;  const float* bias; int nc0;
    if (n0 < KSZ) { W = Wk; bias = bk; nc0 = n0; }
    else          { W = Wv; bias = bv; nc0 = n0 - KSZ; }

    float acc[2][4][4];
    #pragma unroll
    for (int mt = 0; mt < 2; mt++)
        #pragma unroll
        for (int nt = 0; nt < 4; nt++)
            #pragma unroll
            for (int i = 0; i < 4; i++) acc[mt][nt][i] = 0.f;

    for (int k0 = 0; k0 < DIMS; k0 += GBK) {
        // A tile: 128 x 32
        {
            const int col = (tid & 7) * 4;
            const int rbase = tid >> 3;          // 0..31
            #pragma unroll
            for (int r = 0; r < 4; r++) {
                int row = rbase + r * 32;
                float4 v = *(const float4*)(X + (size_t)(m0 + row) * DIMS + k0 + col);
                uint4 t = make_uint4(f2tf(v.x), f2tf(v.y), f2tf(v.z), f2tf(v.w));
                *(uint4*)&As[row * GLDA + col] = t;
            }
        }
        // B tile: W[k0..k0+32][nc0..nc0+64] -> Bs[n][k]
        {
            const int c4 = (tid & 15) * 4;       // 0..60
            const int kb = tid >> 4;             // 0..15
            #pragma unroll
            for (int kk = 0; kk < 2; kk++) {
                int krow = kb + kk * 16;
                float4 w = *(const float4*)(W + (size_t)(k0 + krow) * KSZ + nc0 + c4);
                Bs[(c4 + 0) * GLDB + krow] = f2tf(w.x);
                Bs[(c4 + 1) * GLDB + krow] = f2tf(w.y);
                Bs[(c4 + 2) * GLDB + krow] = f2tf(w.z);
                Bs[(c4 + 3) * GLDB + krow] = f2tf(w.w);
            }
        }
        __syncthreads();

        #pragma unroll
        for (int ks = 0; ks < 4; ks++) {
            const int c = ks * 8 + (lane & 3);
            unsigned a[2][4];
            #pragma unroll
            for (int mt = 0; mt < 2; mt++) {
                int r = wm * 32 + mt * 16 + (lane >> 2);
                a[mt][0] = As[r * GLDA + c];
                a[mt][1] = As[(r + 8) * GLDA + c];
                a[mt][2] = As[r * GLDA + c + 4];
                a[mt][3] = As[(r + 8) * GLDA + c + 4];
            }
            unsigned b[4][2];
            #pragma unroll
            for (int nt = 0; nt < 4; nt++) {
                int n = wn * 32 + nt * 8 + (lane >> 2);
                b[nt][0] = Bs[n * GLDB + c];
                b[nt][1] = Bs[n * GLDB + c + 4];
            }
            #pragma unroll
            for (int mt = 0; mt < 2; mt++)
                #pragma unroll
                for (int nt = 0; nt < 4; nt++)
                    mma_tf32(acc[mt][nt], a[mt][0], a[mt][1], a[mt][2], a[mt][3],
                             b[nt][0], b[nt][1]);
        }
        __syncthreads();
    }

    // epilogue: bias add, write keys or values
    float* dst = (n0 < KSZ) ? g_keys : g_vals;
    #pragma unroll
    for (int mt = 0; mt < 2; mt++) {
        int row = m0 + wm * 32 + mt * 16 + (lane >> 2);
        #pragma unroll
        for (int nt = 0; nt < 4; nt++) {
            int col = nc0 + wn * 32 + nt * 8 + (lane & 3) * 2;
            float b0 = bias[col], b1 = bias[col + 1];
            *(float2*)(dst + (size_t)row * KSZ + col) =
                make_float2(acc[mt][nt][0] + b0, acc[mt][nt][1] + b1);
            *(float2*)(dst + (size_t)(row + 8) * KSZ + col) =
                make_float2(acc[mt][nt][2] + b0, acc[mt][nt][3] + b1);
        }
    }
}

// ---------------------------------------------------------------------------
// Kernel 3: causal flash attention (tf32 mma), writes out[:, 1024:1152]
// BQ=128 queries/block, key tiles of 64. 8 warps; warp w owns query rows
// [16w,16w+16) so softmax rows stay inside one warp (quad shuffles only).
// ---------------------------------------------------------------------------
#define AQ 128
#define AK 64
#define LDQ 132
#define LDP 68

#define SQ_OFF 0
#define SK_OFF (128 * 132)                  // 16896
#define SV_OFF (SK_OFF + 64 * 132)          // 25344
#define SP_OFF (SV_OFF + 64 * 132)          // 33792
#define ATTN_SMEM_U32 (SP_OFF + 128 * 68)   // 42496
#define ATTN_SMEM_BYTES (ATTN_SMEM_U32 * 4) // 169984

extern __shared__ unsigned attn_sm[];

__global__ __launch_bounds__(256, 1) void attn_kernel(float* __restrict__ out) {
    unsigned* Qs = attn_sm + SQ_OFF;
    unsigned* Ks = attn_sm + SK_OFF;
    unsigned* Vs = attn_sm + SV_OFF;
    unsigned* Ps = attn_sm + SP_OFF;

    const int tid = threadIdx.x, lane = tid & 31, wid = tid >> 5;
    const int qt = blockIdx.x;       // 0..15
    const int b  = blockIdx.y;       // 0..7
    const int qbase = qt * AQ;
    const float* keys = g_keys + (size_t)b * SEQ * KSZ;
    const float* vals = g_vals + (size_t)b * SEQ * KSZ;
    const float scale = 0.08838834764831843f;   // 1/sqrt(128), folded into Q

    // load Q tile (scaled, tf32)
    {
        const int c4 = (lane) * 4 >= 0 ? ((tid & 31) * 4) : 0;
        const int rb = tid >> 5;
        #pragma unroll
        for (int p = 0; p < 16; p++) {
            int row = rb + p * 8;
            float4 v = *(const float4*)(keys + (size_t)(qbase + row) * KSZ + c4);
            uint4 t = make_uint4(f2tf(v.x * scale), f2tf(v.y * scale),
                                 f2tf(v.z * scale), f2tf(v.w * scale));
            *(uint4*)&Qs[row * LDQ + c4] = t;
        }
    }

    float O[16][4];
    #pragma unroll
    for (int nt = 0; nt < 16; nt++)
        #pragma unroll
        for (int i = 0; i < 4; i++) O[nt][i] = 0.f;
    float mrow[2] = {-1e30f, -1e30f};
    float lrow[2] = {0.f, 0.f};

    const int nkt = 2 * (qt + 1);
    for (int j = 0; j < nkt; j++) {
        const int kbase = j * AK;
        __syncthreads();   // prior iteration's K/V reads done (also fences Q store, iter 0)
        // load K,V tiles (64 x 128)
        {
            const int c4 = (tid & 31) * 4;
            const int rb = tid >> 5;
            #pragma unroll
            for (int p = 0; p < 8; p++) {
                int row = rb + p * 8;
                float4 kv = *(const float4*)(keys + (size_t)(kbase + row) * KSZ + c4);
                *(uint4*)&Ks[row * LDQ + c4] =
                    make_uint4(f2tf(kv.x), f2tf(kv.y), f2tf(kv.z), f2tf(kv.w));
                float4 vv = *(const float4*)(vals + (size_t)(kbase + row) * KSZ + c4);
                *(uint4*)&Vs[row * LDQ + c4] =
                    make_uint4(f2tf(vv.x), f2tf(vv.y), f2tf(vv.z), f2tf(vv.w));
            }
        }
        __syncthreads();

        // S = Q @ K^T  (warp: 16 rows x 64 keys)
        float s[8][4];
        #pragma unroll
        for (int nt = 0; nt < 8; nt++)
            #pragma unroll
            for (int i = 0; i < 4; i++) s[nt][i] = 0.f;

        #pragma unroll
        for (int ks = 0; ks < 16; ks++) {
            const int r = wid * 16 + (lane >> 2);
            const int c = ks * 8 + (lane & 3);
            unsigned a0 = Qs[r * LDQ + c];
            unsigned a1 = Qs[(r + 8) * LDQ + c];
            unsigned a2 = Qs[r * LDQ + c + 4];
            unsigned a3 = Qs[(r + 8) * LDQ + c + 4];
            #pragma unroll
            for (int nt = 0; nt < 8; nt++) {
                int n = nt * 8 + (lane >> 2);
                unsigned b0 = Ks[n * LDQ + c];
                unsigned b1 = Ks[n * LDQ + c + 4];
                mma_tf32(s[nt], a0, a1, a2, a3, b0, b1);
            }
        }

        // causal mask (reference uses exactly -100 for masked logits)
        if (kbase + AK - 1 > qbase) {
            const int qg0 = qbase + wid * 16 + (lane >> 2);
            const int qg1 = qg0 + 8;
            #pragma unroll
            for (int nt = 0; nt < 8; nt++) {
                int kg = kbase + nt * 8 + (lane & 3) * 2;
                if (kg     > qg0) s[nt][0] = -100.0f;
                if (kg + 1 > qg0) s[nt][1] = -100.0f;
                if (kg     > qg1) s[nt][2] = -100.0f;
                if (kg + 1 > qg1) s[nt][3] = -100.0f;
            }
        }

        // online softmax (rows live in quads: shfl xor 1,2)
        #pragma unroll
        for (int h = 0; h < 2; h++) {
            float mx = -1e30f;
            #pragma unroll
            for (int nt = 0; nt < 8; nt++)
                mx = fmaxf(mx, fmaxf(s[nt][2 * h], s[nt][2 * h + 1]));
            mx = fmaxf(mx, __shfl_xor_sync(0xffffffffu, mx, 1));
            mx = fmaxf(mx, __shfl_xor_sync(0xffffffffu, mx, 2));
            float mnew = fmaxf(mrow[h], mx);
            float alpha = __expf(mrow[h] - mnew);
            mrow[h] = mnew;
            float sum = 0.f;
            #pragma unroll
            for (int nt = 0; nt < 8; nt++) {
                float p0 = __expf(s[nt][2 * h] - mnew);
                float p1 = __expf(s[nt][2 * h + 1] - mnew);
                s[nt][2 * h] = p0; s[nt][2 * h + 1] = p1;
                sum += p0 + p1;
            }
            sum += __shfl_xor_sync(0xffffffffu, sum, 1);
            sum += __shfl_xor_sync(0xffffffffu, sum, 2);
            lrow[h] = lrow[h] * alpha + sum;
            #pragma unroll
            for (int nt = 0; nt < 16; nt++) {
                O[nt][2 * h]     *= alpha;
                O[nt][2 * h + 1] *= alpha;
            }
        }

        // stage P in per-warp smem region (warp-private rows -> syncwarp only)
        {
            const int r = wid * 16 + (lane >> 2);
            #pragma unroll
            for (int nt = 0; nt < 8; nt++) {
                int c = nt * 8 + (lane & 3) * 2;
                *(uint2*)&Ps[r * LDP + c] =
                    make_uint2(f2tf(s[nt][0]), f2tf(s[nt][1]));
                *(uint2*)&Ps[(r + 8) * LDP + c] =
                    make_uint2(f2tf(s[nt][2]), f2tf(s[nt][3]));
            }
        }
        __syncwarp();

        // O += P @ V
        #pragma unroll
        for (int ks = 0; ks < 8; ks++) {
            const int r = wid * 16 + (lane >> 2);
            const int c = ks * 8 + (lane & 3);
            unsigned a0 = Ps[r * LDP + c];
            unsigned a1 = Ps[(r + 8) * LDP + c];
            unsigned a2 = Ps[r * LDP + c + 4];
            unsigned a3 = Ps[(r + 8) * LDP + c + 4];
            const int krow0 = (ks * 8 + (lane & 3)) * LDQ;
            const int krow1 = (ks * 8 + (lane & 3) + 4) * LDQ;
            #pragma unroll
            for (int nt = 0; nt < 16; nt++) {
                int n = nt * 8 + (lane >> 2);
                mma_tf32(O[nt], a0, a1, a2, a3, Vs[krow0 + n], Vs[krow1 + n]);
            }
        }
    }

    // epilogue: normalize, write out[:, 1024:1152]
    {
        float inv0 = 1.0f / lrow[0];
        float inv1 = 1.0f / lrow[1];
        int qg0 = qbase + wid * 16 + (lane >> 2);
        size_t base0 = ((size_t)b * SEQ + qg0) * OUTD + DIMS;
        size_t base1 = base0 + (size_t)8 * OUTD;
        #pragma unroll
        for (int nt = 0; nt < 16; nt++) {
            int c = nt * 8 + (lane & 3) * 2;
            *(float2*)(out + base0 + c) = make_float2(O[nt][0] * inv0, O[nt][1] * inv0);
            *(float2*)(out + base1 + c) = make_float2(O[nt][2] * inv1, O[nt][3] * inv1);
        }
    }
}

// ---------------------------------------------------------------------------
extern "C" void kernel_launch(void* const* d_in, const int* in_sizes, int n_in,
                              void* d_out, int out_size) {
    const float* X  = (const float*)d_in[0];
    const float* Wk = (const float*)d_in[1];
    const float* bk = (const float*)d_in[2];
    const float* Wv = (const float*)d_in[3];
    const float* bv = (const float*)d_in[4];
    // d_in[5] = current_seq_len (fixed 2048; shapes are compile-time here)
    float* out = (float*)d_out;

    copy_x_kernel<<<M_TOTAL, 256>>>(X, out);
    kv_gemm_kernel<<<dim3(M_TOTAL / GBM, 256 / GBN), 256>>>(X, Wk, bk, Wv, bv);

    cudaFuncSetAttribute(attn_kernel, cudaFuncAttributeMaxDynamicSharedMemorySize,
                         ATTN_SMEM_BYTES);
    attn_kernel<<<dim3(SEQ / AQ, BATCH), 256, ATTN_SMEM_BYTES>>>(out);
}

// round 3
// speedup vs baseline: 1.0738x; 1.0738x over previous
#include <cuda_runtime.h>
#include <math.h>

#define DIMS 1024
#define KSZ  128
#define SEQ  2048
#define BATCH 8
#define M_TOTAL (BATCH*SEQ)     // 16384
#define OUTD (DIMS + KSZ)       // 1152

// scratch (allocation-free rule: __device__ globals)
__device__ float g_keys[M_TOTAL * KSZ];
__device__ float g_vals[M_TOTAL * KSZ];

// ---------------------------------------------------------------------------
// helpers
// ---------------------------------------------------------------------------
__device__ __forceinline__ void cp16(unsigned* dst_smem, const float* src) {
    unsigned s = (unsigned)__cvta_generic_to_shared(dst_smem);
    asm volatile("cp.async.cg.shared.global [%0], [%1], 16;" :: "r"(s), "l"(src));
}
#define CP_COMMIT() asm volatile("cp.async.commit_group;")
#define CP_WAIT(n)  asm volatile("cp.async.wait_group %0;" :: "n"(n))

// raw fp32 bits fed as tf32 (HW ignores low 13 mantissa bits)
__device__ __forceinline__ void mma_tf32(float* c,
        unsigned a0, unsigned a1, unsigned a2, unsigned a3,
        unsigned b0, unsigned b1) {
    asm volatile(
        "mma.sync.aligned.m16n8k8.row.col.f32.tf32.tf32.f32 "
        "{%0,%1,%2,%3}, {%4,%5,%6,%7}, {%8,%9}, {%0,%1,%2,%3};"
        : "+f"(c[0]), "+f"(c[1]), "+f"(c[2]), "+f"(c[3])
        : "r"(a0), "r"(a1), "r"(a2), "r"(a3), "r"(b0), "r"(b1));
}

// ---------------------------------------------------------------------------
// Kernel 1: copy minibatch into out[:, 0:1024]   (already ~roofline)
// ---------------------------------------------------------------------------
__global__ void copy_x_kernel(const float* __restrict__ X, float* __restrict__ out) {
    int row = blockIdx.x;
    int c = threadIdx.x * 4;
    float4 v = *(const float4*)(X + (size_t)row * DIMS + c);
    *(float4*)(out + (size_t)row * OUTD + c) = v;
}

// ---------------------------------------------------------------------------
// Kernel 2: KV projection GEMM, cp.async double-buffered, raw-bit tf32
// M=16384, N=256 (cols 0..127 -> Wk, 128..255 -> Wv), Kd=1024
// BM=128, BN=64, BK=32, 256 threads, warps 4x2 (warp tile 32x32)
// A smem: [m][k] (lda 36). B smem: [k][n] (ldb 68) -- cp.async friendly.
// ---------------------------------------------------------------------------
#define GBM 128
#define GBN 64
#define GBK 32
#define GLDA 36
#define GLDB 68
#define GEMM_AS (GBM * GLDA)               // 4608
#define GEMM_BS (GBK * GLDB)               // 2176
#define GEMM_SMEM_U32 (2*GEMM_AS + 2*GEMM_BS)
#define GEMM_SMEM_BYTES (GEMM_SMEM_U32 * 4)   // 54272

extern __shared__ unsigned dyn_sm[];

__global__ __launch_bounds__(256) void kv_gemm_kernel(
        const float* __restrict__ X,
        const float* __restrict__ Wk, const float* __restrict__ bk,
        const float* __restrict__ Wv, const float* __restrict__ bv) {
    unsigned* Asb[2] = { dyn_sm, dyn_sm + GEMM_AS };
    unsigned* Bsb[2] = { dyn_sm + 2*GEMM_AS, dyn_sm + 2*GEMM_AS + GEMM_BS };

    const int tid = threadIdx.x, lane = tid & 31, wid = tid >> 5;
    const int wm = wid & 3, wn = wid >> 2;
    const int m0 = blockIdx.x * GBM;
    const int n0 = blockIdx.y * GBN;

    const float* W;  const float* bias; int nc0;
    if (n0 < KSZ) { W = Wk; bias = bk; nc0 = n0; }
    else          { W = Wv; bias = bv; nc0 = n0 - KSZ; }

    // loader: A tile 128x32, B tile 32x64
    const int ar = tid >> 1, ac0 = (tid & 1) * 16;
    const int br = tid >> 3, bc0 = (tid & 7) * 8;

    #define GEMM_LOAD(buf, k0) do {                                           \
        const float* asrc = X + (size_t)(m0 + ar) * DIMS + (k0) + ac0;        \
        unsigned* ad = Asb[buf] + ar * GLDA + ac0;                            \
        cp16(ad, asrc); cp16(ad+4, asrc+4); cp16(ad+8, asrc+8); cp16(ad+12, asrc+12); \
        const float* bsrc = W + (size_t)((k0) + br) * KSZ + nc0 + bc0;        \
        unsigned* bd = Bsb[buf] + br * GLDB + bc0;                            \
        cp16(bd, bsrc); cp16(bd+4, bsrc+4);                                   \
    } while (0)

    float acc[2][4][4];
    #pragma unroll
    for (int mt = 0; mt < 2; mt++)
        #pragma unroll
        for (int nt = 0; nt < 4; nt++)
            #pragma unroll
            for (int i = 0; i < 4; i++) acc[mt][nt][i] = 0.f;

    GEMM_LOAD(0, 0);
    CP_COMMIT();

    const int NK = DIMS / GBK;   // 32
    for (int kk = 0; kk < NK; kk++) {
        if (kk + 1 < NK) {
            GEMM_LOAD((kk + 1) & 1, (kk + 1) * GBK);
            CP_COMMIT();
            CP_WAIT(1);
        } else {
            CP_WAIT(0);
        }
        __syncthreads();

        const unsigned* As = Asb[kk & 1];
        const unsigned* Bs = Bsb[kk & 1];
        #pragma unroll
        for (int ks = 0; ks < 4; ks++) {
            const int c = ks * 8 + (lane & 3);
            unsigned a[2][4];
            #pragma unroll
            for (int mt = 0; mt < 2; mt++) {
                int r = wm * 32 + mt * 16 + (lane >> 2);
                a[mt][0] = As[r * GLDA + c];
                a[mt][1] = As[(r + 8) * GLDA + c];
                a[mt][2] = As[r * GLDA + c + 4];
                a[mt][3] = As[(r + 8) * GLDA + c + 4];
            }
            unsigned b[4][2];
            #pragma unroll
            for (int nt = 0; nt < 4; nt++) {
                int n = wn * 32 + nt * 8 + (lane >> 2);
                b[nt][0] = Bs[c * GLDB + n];
                b[nt][1] = Bs[(c + 4) * GLDB + n];
            }
            #pragma unroll
            for (int mt = 0; mt < 2; mt++)
                #pragma unroll
                for (int nt = 0; nt < 4; nt++)
                    mma_tf32(acc[mt][nt], a[mt][0], a[mt][1], a[mt][2], a[mt][3],
                             b[nt][0], b[nt][1]);
        }
        __syncthreads();
    }

    float* dst = (n0 < KSZ) ? g_keys : g_vals;
    #pragma unroll
    for (int mt = 0; mt < 2; mt++) {
        int row = m0 + wm * 32 + mt * 16 + (lane >> 2);
        #pragma unroll
        for (int nt = 0; nt < 4; nt++) {
            int col = nc0 + wn * 32 + nt * 8 + (lane & 3) * 2;
            float b0 = bias[col], b1 = bias[col + 1];
            *(float2*)(dst + (size_t)row * KSZ + col) =
                make_float2(acc[mt][nt][0] + b0, acc[mt][nt][1] + b1);
            *(float2*)(dst + (size_t)(row + 8) * KSZ + col) =
                make_float2(acc[mt][nt][2] + b0, acc[mt][nt][3] + b1);
        }
    }
}

// ---------------------------------------------------------------------------
// Kernel 3: causal flash attention, balanced via query-tile pairing.
// AQ=64 queries/tile, AK=64 keys/iter. 128 threads (4 warps x 16 query rows).
// Block p handles qt = p, then qt = 31-p  -> exactly 33 key iterations/block.
// Grid = 16 pairs x 8 batches = 128 blocks = one wave. cp.async double buffer.
// ---------------------------------------------------------------------------
#define AQ 64
#define AK 64
#define LDQ 132
#define LDP 68
#define NQT (SEQ / AQ)     // 32

#define SQ_OFF  0
#define SK0_OFF (64 * 132)                  // 8448
#define SK1_OFF (SK0_OFF + 64 * 132)
#define SV0_OFF (SK1_OFF + 64 * 132)
#define SV1_OFF (SV0_OFF + 64 * 132)
#define SP_OFF  (SV1_OFF + 64 * 132)        // 42240
#define ATTN_SMEM_U32 (SP_OFF + 64 * 68)    // 46592
#define ATTN_SMEM_BYTES (ATTN_SMEM_U32 * 4) // 186368

__global__ __launch_bounds__(128, 1) void attn_kernel(float* __restrict__ out) {
    unsigned* Qs = dyn_sm + SQ_OFF;
    unsigned* Ksb[2] = { dyn_sm + SK0_OFF, dyn_sm + SK1_OFF };
    unsigned* Vsb[2] = { dyn_sm + SV0_OFF, dyn_sm + SV1_OFF };
    unsigned* Ps = dyn_sm + SP_OFF;

    const int tid = threadIdx.x, lane = tid & 31, wid = tid >> 5;
    const int pairIdx = blockIdx.x;  // 0..15
    const int b = blockIdx.y;        // 0..7
    const float* keys = g_keys + (size_t)b * SEQ * KSZ;
    const float* vals = g_vals + (size_t)b * SEQ * KSZ;
    const float scale = 0.08838834764831843f;   // 1/sqrt(128)

    const int ldr = tid >> 1;            // 0..63
    const int ldc = (tid & 1) * 64;      // 0 or 64

    #define LOAD_KV(buf, kbase) do {                                          \
        const float* ksrc = keys + (size_t)((kbase) + ldr) * KSZ + ldc;       \
        const float* vsrc = vals + (size_t)((kbase) + ldr) * KSZ + ldc;       \
        unsigned* kd = Ksb[buf] + ldr * LDQ + ldc;                            \
        unsigned* vd = Vsb[buf] + ldr * LDQ + ldc;                            \
        _Pragma("unroll")                                                     \
        for (int i = 0; i < 16; i++) {                                        \
            cp16(kd + i * 4, ksrc + i * 4);                                   \
            cp16(vd + i * 4, vsrc + i * 4);                                   \
        }                                                                     \
    } while (0)

    for (int half = 0; half < 2; half++) {
        const int qt = (half == 0) ? pairIdx : (NQT - 1 - pairIdx);
        const int qbase = qt * AQ;
        const int nkt = qt + 1;

        // load Q tile (raw bits) + first K/V tile, one group
        {
            const float* qsrc = keys + (size_t)(qbase + ldr) * KSZ + ldc;
            unsigned* qd = Qs + ldr * LDQ + ldc;
            #pragma unroll
            for (int i = 0; i < 16; i++) cp16(qd + i * 4, qsrc + i * 4);
        }
        LOAD_KV(0, 0);
        CP_COMMIT();

        float O[16][4];
        #pragma unroll
        for (int nt = 0; nt < 16; nt++)
            #pragma unroll
            for (int i = 0; i < 4; i++) O[nt][i] = 0.f;
        float mrow[2] = {-1e30f, -1e30f};
        float lrow[2] = {0.f, 0.f};

        for (int j = 0; j < nkt; j++) {
            if (j + 1 < nkt) {
                LOAD_KV((j + 1) & 1, (j + 1) * AK);
                CP_COMMIT();
                CP_WAIT(1);
            } else {
                CP_WAIT(0);
            }
            __syncthreads();

            const unsigned* Ks = Ksb[j & 1];
            const unsigned* Vs = Vsb[j & 1];
            const int kbase = j * AK;

            // S = Q @ K^T  (warp: 16 rows x 64 keys)
            float s[8][4];
            #pragma unroll
            for (int nt = 0; nt < 8; nt++)
                #pragma unroll
                for (int i = 0; i < 4; i++) s[nt][i] = 0.f;

            #pragma unroll
            for (int ks = 0; ks < 16; ks++) {
                const int r = wid * 16 + (lane >> 2);
                const int c = ks * 8 + (lane & 3);
                unsigned a0 = Qs[r * LDQ + c];
                unsigned a1 = Qs[(r + 8) * LDQ + c];
                unsigned a2 = Qs[r * LDQ + c + 4];
                unsigned a3 = Qs[(r + 8) * LDQ + c + 4];
                #pragma unroll
                for (int nt = 0; nt < 8; nt++) {
                    int n = nt * 8 + (lane >> 2);
                    mma_tf32(s[nt], a0, a1, a2, a3,
                             Ks[n * LDQ + c], Ks[n * LDQ + c + 4]);
                }
            }

            // scale
            #pragma unroll
            for (int nt = 0; nt < 8; nt++)
                #pragma unroll
                for (int i = 0; i < 4; i++) s[nt][i] *= scale;

            // causal mask (only the diagonal tile), exactly -100 like reference
            if (j == nkt - 1) {
                const int qg0 = qbase + wid * 16 + (lane >> 2);
                const int qg1 = qg0 + 8;
                #pragma unroll
                for (int nt = 0; nt < 8; nt++) {
                    int kg = kbase + nt * 8 + (lane & 3) * 2;
                    if (kg     > qg0) s[nt][0] = -100.0f;
                    if (kg + 1 > qg0) s[nt][1] = -100.0f;
                    if (kg     > qg1) s[nt][2] = -100.0f;
                    if (kg + 1 > qg1) s[nt][3] = -100.0f;
                }
            }

            // online softmax (rows in quads: shfl xor 1,2)
            #pragma unroll
            for (int h = 0; h < 2; h++) {
                float mx = -1e30f;
                #pragma unroll
                for (int nt = 0; nt < 8; nt++)
                    mx = fmaxf(mx, fmaxf(s[nt][2 * h], s[nt][2 * h + 1]));
                mx = fmaxf(mx, __shfl_xor_sync(0xffffffffu, mx, 1));
                mx = fmaxf(mx, __shfl_xor_sync(0xffffffffu, mx, 2));
                float mnew = fmaxf(mrow[h], mx);
                float alpha = __expf(mrow[h] - mnew);
                mrow[h] = mnew;
                float sum = 0.f;
                #pragma unroll
                for (int nt = 0; nt < 8; nt++) {
                    float p0 = __expf(s[nt][2 * h] - mnew);
                    float p1 = __expf(s[nt][2 * h + 1] - mnew);
                    s[nt][2 * h] = p0; s[nt][2 * h + 1] = p1;
                    sum += p0 + p1;
                }
                sum += __shfl_xor_sync(0xffffffffu, sum, 1);
                sum += __shfl_xor_sync(0xffffffffu, sum, 2);
                lrow[h] = lrow[h] * alpha + sum;
                #pragma unroll
                for (int nt = 0; nt < 16; nt++) {
                    O[nt][2 * h]     *= alpha;
                    O[nt][2 * h + 1] *= alpha;
                }
            }

            // stage P in per-warp smem rows (raw fp32 bits -> tf32 by truncation)
            {
                const int r = wid * 16 + (lane >> 2);
                #pragma unroll
                for (int nt = 0; nt < 8; nt++) {
                    int c = nt * 8 + (lane & 3) * 2;
                    *(uint2*)&Ps[r * LDP + c] =
                        make_uint2(__float_as_uint(s[nt][0]), __float_as_uint(s[nt][1]));
                    *(uint2*)&Ps[(r + 8) * LDP + c] =
                        make_uint2(__float_as_uint(s[nt][2]), __float_as_uint(s[nt][3]));
                }
            }
            __syncwarp();

            // O += P @ V
            #pragma unroll
            for (int ks = 0; ks < 8; ks++) {
                const int r = wid * 16 + (lane >> 2);
                const int c = ks * 8 + (lane & 3);
                unsigned a0 = Ps[r * LDP + c];
                unsigned a1 = Ps[(r + 8) * LDP + c];
                unsigned a2 = Ps[r * LDP + c + 4];
                unsigned a3 = Ps[(r + 8) * LDP + c + 4];
                const int kr0 = (ks * 8 + (lane & 3)) * LDQ;
                const int kr1 = kr0 + 4 * LDQ;
                #pragma unroll
                for (int nt = 0; nt < 16; nt++) {
                    int n = nt * 8 + (lane >> 2);
                    mma_tf32(O[nt], a0, a1, a2, a3, Vs[kr0 + n], Vs[kr1 + n]);
                }
            }
            __syncthreads();
        }

        // epilogue: normalize, write out[:, 1024:1152]
        {
            float inv0 = 1.0f / lrow[0];
            float inv1 = 1.0f / lrow[1];
            int qg0 = qbase + wid * 16 + (lane >> 2);
            size_t base0 = ((size_t)b * SEQ + qg0) * OUTD + DIMS;
            size_t base1 = base0 + (size_t)8 * OUTD;
            #pragma unroll
            for (int nt = 0; nt < 16; nt++) {
                int c = nt * 8 + (lane & 3) * 2;
                *(float2*)(out + base0 + c) = make_float2(O[nt][0] * inv0, O[nt][1] * inv0);
                *(float2*)(out + base1 + c) = make_float2(O[nt][2] * inv1, O[nt][3] * inv1);
            }
        }
        // no extra sync needed: last iteration ended with __syncthreads()
    }
}

// ---------------------------------------------------------------------------
extern "C" void kernel_launch(void* const* d_in, const int* in_sizes, int n_in,
                              void* d_out, int out_size) {
    const float* X  = (const float*)d_in[0];
    const float* Wk = (const float*)d_in[1];
    const float* bk = (const float*)d_in[2];
    const float* Wv = (const float*)d_in[3];
    const float* bv = (const float*)d_in[4];
    float* out = (float*)d_out;

    copy_x_kernel<<<M_TOTAL, 256>>>(X, out);

    cudaFuncSetAttribute(kv_gemm_kernel, cudaFuncAttributeMaxDynamicSharedMemorySize,
                         GEMM_SMEM_BYTES);
    kv_gemm_kernel<<<dim3(M_TOTAL / GBM, 256 / GBN), 256, GEMM_SMEM_BYTES>>>(
        X, Wk, bk, Wv, bv);

    cudaFuncSetAttribute(attn_kernel, cudaFuncAttributeMaxDynamicSharedMemorySize,
                         ATTN_SMEM_BYTES);
    attn_kernel<<<dim3(NQT / 2, BATCH), 128, ATTN_SMEM_BYTES>>>(out);
}

// round 5
// speedup vs baseline: 1.0882x; 1.0134x over previous
#include <cuda_runtime.h>
#include <math.h>

#define DIMS 1024
#define KSZ  128
#define SEQ  2048
#define BATCH 8
#define M_TOTAL (BATCH*SEQ)     // 16384
#define OUTD (DIMS + KSZ)       // 1152

// scratch, zero-initialized at module load; pad rows stay 0 forever (OOB-safe
// for the AK=48 overhang reads; overhang keys are causally masked anyway).
__device__ float g_keys[(M_TOTAL + 64) * KSZ];
__device__ float g_vals[(M_TOTAL + 64) * KSZ];

// ---------------------------------------------------------------------------
// helpers
// ---------------------------------------------------------------------------
__device__ __forceinline__ void cp16(unsigned* dst_smem, const float* src) {
    unsigned s = (unsigned)__cvta_generic_to_shared(dst_smem);
    asm volatile("cp.async.cg.shared.global [%0], [%1], 16;" :: "r"(s), "l"(src));
}
#define CP_COMMIT() asm volatile("cp.async.commit_group;")
#define CP_WAIT(n)  asm volatile("cp.async.wait_group %0;" :: "n"(n))

// fp32 bits fed as tf32. HW truncates the low 13 mantissa bits; adding 0x1000
// first gives round-to-nearest (halves quantization error, removes bias).
#define RND_TF32(u) ((u) + 0x1000u)

__device__ __forceinline__ void mma_tf32(float* c,
        unsigned a0, unsigned a1, unsigned a2, unsigned a3,
        unsigned b0, unsigned b1) {
    asm volatile(
        "mma.sync.aligned.m16n8k8.row.col.f32.tf32.tf32.f32 "
        "{%0,%1,%2,%3}, {%4,%5,%6,%7}, {%8,%9}, {%0,%1,%2,%3};"
        : "+f"(c[0]), "+f"(c[1]), "+f"(c[2]), "+f"(c[3])
        : "r"(a0), "r"(a1), "r"(a2), "r"(a3), "r"(b0), "r"(b1));
}

extern __shared__ unsigned dyn_sm[];

// ---------------------------------------------------------------------------
// Kernel 1: KV projection GEMM, cp.async double-buffered, rounded tf32
// M=16384, N=256, Kd=1024. BM=128, BN=64, BK=32, 256 threads, 2 CTAs/SM.
// ---------------------------------------------------------------------------
#define GBM 128
#define GBN 64
#define GBK 32
#define GLDA 36
#define GLDB 68
#define GEMM_AS (GBM * GLDA)               // 4608
#define GEMM_BS (GBK * GLDB)               // 2176
#define GEMM_SMEM_U32 (2*GEMM_AS + 2*GEMM_BS)
#define GEMM_SMEM_BYTES (GEMM_SMEM_U32 * 4)   // 54272

__global__ __launch_bounds__(256, 2) void kv_gemm_kernel(
        const float* __restrict__ X,
        const float* __restrict__ Wk, const float* __restrict__ bk,
        const float* __restrict__ Wv, const float* __restrict__ bv) {
    unsigned* Asb[2] = { dyn_sm, dyn_sm + GEMM_AS };
    unsigned* Bsb[2] = { dyn_sm + 2*GEMM_AS, dyn_sm + 2*GEMM_AS + GEMM_BS };

    const int tid = threadIdx.x, lane = tid & 31, wid = tid >> 5;
    const int wm = wid & 3, wn = wid >> 2;
    const int m0 = blockIdx.x * GBM;
    const int n0 = blockIdx.y * GBN;

    const float* W;  const float* bias; int nc0;
    if (n0 < KSZ) { W = Wk; bias = bk; nc0 = n0; }
    else          { W = Wv; bias = bv; nc0 = n0 - KSZ; }

    const int ar = tid >> 1, ac0 = (tid & 1) * 16;
    const int br = tid >> 3, bc0 = (tid & 7) * 8;

    #define GEMM_LOAD(buf, k0) do {                                           \
        const float* asrc = X + (size_t)(m0 + ar) * DIMS + (k0) + ac0;        \
        unsigned* ad = Asb[buf] + ar * GLDA + ac0;                            \
        cp16(ad, asrc); cp16(ad+4, asrc+4); cp16(ad+8, asrc+8); cp16(ad+12, asrc+12); \
        const float* bsrc = W + (size_t)((k0) + br) * KSZ + nc0 + bc0;        \
        unsigned* bd = Bsb[buf] + br * GLDB + bc0;                            \
        cp16(bd, bsrc); cp16(bd+4, bsrc+4);                                   \
    } while (0)

    float acc[2][4][4];
    #pragma unroll
    for (int mt = 0; mt < 2; mt++)
        #pragma unroll
        for (int nt = 0; nt < 4; nt++)
            #pragma unroll
            for (int i = 0; i < 4; i++) acc[mt][nt][i] = 0.f;

    GEMM_LOAD(0, 0);
    CP_COMMIT();

    const int NK = DIMS / GBK;   // 32
    for (int kk = 0; kk < NK; kk++) {
        if (kk + 1 < NK) {
            GEMM_LOAD((kk + 1) & 1, (kk + 1) * GBK);
            CP_COMMIT();
            CP_WAIT(1);
        } else {
            CP_WAIT(0);
        }
        __syncthreads();

        const unsigned* As = Asb[kk & 1];
        const unsigned* Bs = Bsb[kk & 1];
        #pragma unroll
        for (int ks = 0; ks < 4; ks++) {
            const int c = ks * 8 + (lane & 3);
            unsigned a[2][4];
            #pragma unroll
            for (int mt = 0; mt < 2; mt++) {
                int r = wm * 32 + mt * 16 + (lane >> 2);
                a[mt][0] = RND_TF32(As[r * GLDA + c]);
                a[mt][1] = RND_TF32(As[(r + 8) * GLDA + c]);
                a[mt][2] = RND_TF32(As[r * GLDA + c + 4]);
                a[mt][3] = RND_TF32(As[(r + 8) * GLDA + c + 4]);
            }
            unsigned b[4][2];
            #pragma unroll
            for (int nt = 0; nt < 4; nt++) {
                int n = wn * 32 + nt * 8 + (lane >> 2);
                b[nt][0] = RND_TF32(Bs[c * GLDB + n]);
                b[nt][1] = RND_TF32(Bs[(c + 4) * GLDB + n]);
            }
            #pragma unroll
            for (int mt = 0; mt < 2; mt++)
                #pragma unroll
                for (int nt = 0; nt < 4; nt++)
                    mma_tf32(acc[mt][nt], a[mt][0], a[mt][1], a[mt][2], a[mt][3],
                             b[nt][0], b[nt][1]);
        }
        __syncthreads();
    }

    float* dst = (n0 < KSZ) ? g_keys : g_vals;
    #pragma unroll
    for (int mt = 0; mt < 2; mt++) {
        int row = m0 + wm * 32 + mt * 16 + (lane >> 2);
        #pragma unroll
        for (int nt = 0; nt < 4; nt++) {
            int col = nc0 + wn * 32 + nt * 8 + (lane & 3) * 2;
            float b0 = bias[col], b1 = bias[col + 1];
            *(float2*)(dst + (size_t)row * KSZ + col) =
                make_float2(acc[mt][nt][0] + b0, acc[mt][nt][1] + b1);
            *(float2*)(dst + (size_t)(row + 8) * KSZ + col) =
                make_float2(acc[mt][nt][2] + b0, acc[mt][nt][3] + b1);
        }
    }
}

// ---------------------------------------------------------------------------
// Kernel 2: causal flash attention + X copy, dual warp-group design.
// 256 threads: warps 0-3 (group 0) do qt = pairIdx; warps 4-7 (group 1) do
// qt = 31-pairIdx, concurrently, with per-group named barriers. Every SMSP
// gets 2 independent warps -> LDS latency hidden. Each group also copies its
// 64 X rows into out[:,0:1024] (replaces the standalone copy kernel).
// AQ=64, AK=48, double-buffered K/V per group, Q held in registers.
// ---------------------------------------------------------------------------
#define AQ 64
#define AK 48
#define LDK 132
#define LDP 52
#define NQT (SEQ / AQ)     // 32
#define NT_S (AK / 8)      // 6

// per-group smem layout (words): K0,K1,V0,V1 = 48*132 each, P = 64*52
#define KV_TILE (AK * LDK)              // 6336
#define GOFF_K0 0
#define GOFF_K1 (KV_TILE)
#define GOFF_V0 (2 * KV_TILE)
#define GOFF_V1 (3 * KV_TILE)
#define GOFF_P  (4 * KV_TILE)           // 25344
#define GRP_WORDS (GOFF_P + AQ * LDP)   // 28672
#define ATTN_SMEM_BYTES (2 * GRP_WORDS * 4)   // 229376

__global__ __launch_bounds__(256, 1) void attn_kernel(
        const float* __restrict__ X, float* __restrict__ out) {
    const int tid = threadIdx.x, lane = tid & 31, wid = tid >> 5;
    const int grp = wid >> 2;        // 0 or 1
    const int wg  = wid & 3;         // warp within group
    const int gt  = tid & 127;       // thread within group
    const int barid = grp + 1;
    #define GBAR() asm volatile("bar.sync %0, 128;" :: "r"(barid))

    unsigned* gs = dyn_sm + grp * GRP_WORDS;
    unsigned* Kb[2] = { gs + GOFF_K0, gs + GOFF_K1 };
    unsigned* Vb[2] = { gs + GOFF_V0, gs + GOFF_V1 };
    unsigned* Ps    = gs + GOFF_P;

    const int pairIdx = blockIdx.x;              // 0..15
    const int b = blockIdx.y;                    // 0..7
    const int qt = grp ? (NQT - 1 - pairIdx) : pairIdx;
    const int qbase = qt * AQ;
    const int nkt = (qbase + AQ + AK - 1) / AK;  // tiles of 48 covering keys
    const float* keys = g_keys + (size_t)b * SEQ * KSZ;
    const float* vals = g_vals + (size_t)b * SEQ * KSZ;
    const float scale = 0.08838834764831843f;    // 1/sqrt(128)

    // K/V tile loader: 48 rows x 128 cols = 1536 float4, 12 per thread
    #define LOAD_KV(buf, kbase) do {                                          \
        _Pragma("unroll")                                                     \
        for (int i = 0; i < 12; i++) {                                        \
            int idx = gt + i * 128;                                           \
            int row = idx >> 5, c4 = (idx & 31) * 4;                          \
            cp16(Kb[buf] + row * LDK + c4,                                    \
                 keys + (size_t)((kbase) + row) * KSZ + c4);                  \
            cp16(Vb[buf] + row * LDK + c4,                                    \
                 vals + (size_t)((kbase) + row) * KSZ + c4);                  \
        }                                                                     \
    } while (0)

    // --- stage Q (64x128) through K0/K1 region, then extract to registers ---
    #pragma unroll
    for (int i = 0; i < 16; i++) {
        int idx = gt + i * 128;
        int row = idx >> 5, c4 = (idx & 31) * 4;
        cp16(gs + row * LDK + c4, keys + (size_t)(qbase + row) * KSZ + c4);
    }
    CP_COMMIT();

    // --- copy this group's 64 X rows into out[:,0:1024] (overlaps Q load) ---
    {
        int row = gt >> 1;
        int coff = (gt & 1) * 512;
        const float4* src = (const float4*)(X + (size_t)(b * SEQ + qbase + row) * DIMS + coff);
        float4* dst = (float4*)(out + (size_t)(b * SEQ + qbase + row) * OUTD + coff);
        #pragma unroll 8
        for (int i = 0; i < 128; i++) dst[i] = src[i];
    }

    CP_WAIT(0);
    GBAR();

    // Q fragments: 16 k-steps x 4 regs, scaled + rounded
    unsigned qa[16][4];
    {
        const int r0 = wg * 16 + (lane >> 2);
        #pragma unroll
        for (int ks = 0; ks < 16; ks++) {
            const int c = ks * 8 + (lane & 3);
            unsigned u0 = gs[r0 * LDK + c];
            unsigned u1 = gs[(r0 + 8) * LDK + c];
            unsigned u2 = gs[r0 * LDK + c + 4];
            unsigned u3 = gs[(r0 + 8) * LDK + c + 4];
            qa[ks][0] = RND_TF32(__float_as_uint(__uint_as_float(u0) * scale));
            qa[ks][1] = RND_TF32(__float_as_uint(__uint_as_float(u1) * scale));
            qa[ks][2] = RND_TF32(__float_as_uint(__uint_as_float(u2) * scale));
            qa[ks][3] = RND_TF32(__float_as_uint(__uint_as_float(u3) * scale));
        }
    }
    GBAR();

    LOAD_KV(0, 0);
    CP_COMMIT();

    float O[16][4];
    #pragma unroll
    for (int nt = 0; nt < 16; nt++)
        #pragma unroll
        for (int i = 0; i < 4; i++) O[nt][i] = 0.f;
    float mrow[2] = {-1e30f, -1e30f};
    float lrow[2] = {0.f, 0.f};

    for (int j = 0; j < nkt; j++) {
        if (j + 1 < nkt) {
            LOAD_KV((j + 1) & 1, (j + 1) * AK);   // buffer was drained at end of j-1
            CP_COMMIT();
            CP_WAIT(1);
        } else {
            CP_WAIT(0);
        }
        GBAR();

        const unsigned* Ks = Kb[j & 1];
        const unsigned* Vs = Vb[j & 1];
        const int kbase = j * AK;

        // S = Q @ K^T  (warp: 16 rows x 48 keys)
        float s[NT_S][4];
        #pragma unroll
        for (int nt = 0; nt < NT_S; nt++)
            #pragma unroll
            for (int i = 0; i < 4; i++) s[nt][i] = 0.f;

        #pragma unroll
        for (int ks = 0; ks < 16; ks++) {
            const int c = ks * 8 + (lane & 3);
            #pragma unroll
            for (int nt = 0; nt < NT_S; nt++) {
                int n = nt * 8 + (lane >> 2);
                mma_tf32(s[nt], qa[ks][0], qa[ks][1], qa[ks][2], qa[ks][3],
                         Ks[n * LDK + c], Ks[n * LDK + c + 4]);
            }
        }

        // causal mask (any tile straddling/beyond the diagonal), exactly -100
        if (kbase + AK - 1 > qbase) {
            const int qg0 = qbase + wg * 16 + (lane >> 2);
            const int qg1 = qg0 + 8;
            #pragma unroll
            for (int nt = 0; nt < NT_S; nt++) {
                int kg = kbase + nt * 8 + (lane & 3) * 2;
                if (kg     > qg0) s[nt][0] = -100.0f;
                if (kg + 1 > qg0) s[nt][1] = -100.0f;
                if (kg     > qg1) s[nt][2] = -100.0f;
                if (kg + 1 > qg1) s[nt][3] = -100.0f;
            }
        }

        // online softmax (rows live in quads: shfl xor 1,2)
        #pragma unroll
        for (int h = 0; h < 2; h++) {
            float mx = -1e30f;
            #pragma unroll
            for (int nt = 0; nt < NT_S; nt++)
                mx = fmaxf(mx, fmaxf(s[nt][2 * h], s[nt][2 * h + 1]));
            mx = fmaxf(mx, __shfl_xor_sync(0xffffffffu, mx, 1));
            mx = fmaxf(mx, __shfl_xor_sync(0xffffffffu, mx, 2));
            float mnew = fmaxf(mrow[h], mx);
            float alpha = __expf(mrow[h] - mnew);
            mrow[h] = mnew;
            float sum = 0.f;
            #pragma unroll
            for (int nt = 0; nt < NT_S; nt++) {
                float p0 = __expf(s[nt][2 * h] - mnew);
                float p1 = __expf(s[nt][2 * h + 1] - mnew);
                s[nt][2 * h] = p0; s[nt][2 * h + 1] = p1;
                sum += p0 + p1;
            }
            sum += __shfl_xor_sync(0xffffffffu, sum, 1);
            sum += __shfl_xor_sync(0xffffffffu, sum, 2);
            lrow[h] = lrow[h] * alpha + sum;
            #pragma unroll
            for (int nt = 0; nt < 16; nt++) {
                O[nt][2 * h]     *= alpha;
                O[nt][2 * h + 1] *= alpha;
            }
        }

        // stage P in per-warp smem rows (raw bits; P in [0,1])
        {
            const int r = wg * 16 + (lane >> 2);
            #pragma unroll
            for (int nt = 0; nt < NT_S; nt++) {
                int c = nt * 8 + (lane & 3) * 2;
                *(uint2*)&Ps[r * LDP + c] =
                    make_uint2(__float_as_uint(s[nt][0]), __float_as_uint(s[nt][1]));
                *(uint2*)&Ps[(r + 8) * LDP + c] =
                    make_uint2(__float_as_uint(s[nt][2]), __float_as_uint(s[nt][3]));
            }
        }
        __syncwarp();

        // O += P @ V
        #pragma unroll
        for (int ks = 0; ks < NT_S; ks++) {
            const int r = wg * 16 + (lane >> 2);
            const int c = ks * 8 + (lane & 3);
            unsigned a0 = Ps[r * LDP + c];
            unsigned a1 = Ps[(r + 8) * LDP + c];
            unsigned a2 = Ps[r * LDP + c + 4];
            unsigned a3 = Ps[(r + 8) * LDP + c + 4];
            const int kr0 = (ks * 8 + (lane & 3)) * LDK;
            const int kr1 = kr0 + 4 * LDK;
            #pragma unroll
            for (int nt = 0; nt < 16; nt++) {
                int n = nt * 8 + (lane >> 2);
                mma_tf32(O[nt], a0, a1, a2, a3, Vs[kr0 + n], Vs[kr1 + n]);
            }
        }
        GBAR();
    }

    // epilogue: normalize, write out[:, 1024:1152]
    {
        float inv0 = 1.0f / lrow[0];
        float inv1 = 1.0f / lrow[1];
        int qg0 = qbase + wg * 16 + (lane >> 2);
        size_t base0 = ((size_t)b * SEQ + qg0) * OUTD + DIMS;
        size_t base1 = base0 + (size_t)8 * OUTD;
        #pragma unroll
        for (int nt = 0; nt < 16; nt++) {
            int c = nt * 8 + (lane & 3) * 2;
            *(float2*)(out + base0 + c) = make_float2(O[nt][0] * inv0, O[nt][1] * inv0);
            *(float2*)(out + base1 + c) = make_float2(O[nt][2] * inv1, O[nt][3] * inv1);
        }
    }
}

// ---------------------------------------------------------------------------
extern "C" void kernel_launch(void* const* d_in, const int* in_sizes, int n_in,
                              void* d_out, int out_size) {
    const float* X  = (const float*)d_in[0];
    const float* Wk = (const float*)d_in[1];
    const float* bk = (const float*)d_in[2];
    const float* Wv = (const float*)d_in[3];
    const float* bv = (const float*)d_in[4];
    float* out = (float*)d_out;

    cudaFuncSetAttribute(kv_gemm_kernel, cudaFuncAttributeMaxDynamicSharedMemorySize,
                         GEMM_SMEM_BYTES);
    kv_gemm_kernel<<<dim3(M_TOTAL / GBM, 256 / GBN), 256, GEMM_SMEM_BYTES>>>(
        X, Wk, bk, Wv, bv);

    cudaFuncSetAttribute(attn_kernel, cudaFuncAttributeMaxDynamicSharedMemorySize,
                         ATTN_SMEM_BYTES);
    attn_kernel<<<dim3(NQT / 2, BATCH), 256, ATTN_SMEM_BYTES>>>(X, out);
}

// round 9
// speedup vs baseline: 2.6051x; 2.3939x over previous
#include <cuda_runtime.h>
#include <cuda_fp16.h>
#include <math.h>

#define DIMS 1024
#define KSZ  128
#define SEQ  2048
#define BATCH 8
#define M_TOTAL (BATCH*SEQ)     // 16384
#define OUTD (DIMS + KSZ)       // 1152

// scratch (allocation-free rule: __device__ globals)
__device__ __half g_xh[M_TOTAL * DIMS];            // 32MB  X in fp16
__device__ __half g_wth[2 * KSZ * DIMS];           // [n=256][k=1024] W^T fp16
__device__ __half g_keys_h[M_TOTAL * KSZ];         // 4MB   keys fp16 [tok][dim]
__device__ __half g_valsT_h[(size_t)BATCH * KSZ * SEQ]; // 4MB vals^T fp16 [b][dim][tok]

// ---------------------------------------------------------------------------
// helpers
// ---------------------------------------------------------------------------
__device__ __forceinline__ void cp16a(unsigned daddr, const void* src) {
    asm volatile("cp.async.cg.shared.global [%0], [%1], 16;" :: "r"(daddr), "l"(src));
}
#define CP_COMMIT() asm volatile("cp.async.commit_group;")
#define CP_WAIT(n)  asm volatile("cp.async.wait_group %0;" :: "n"(n))

// fp16 mma m16n8k16, f32 accumulate (plain sm_100-legal)
__device__ __forceinline__ void mma_f16(float* c,
        unsigned a0, unsigned a1, unsigned a2, unsigned a3,
        unsigned b0, unsigned b1) {
    asm volatile(
        "mma.sync.aligned.m16n8k16.row.col.f32.f16.f16.f32 "
        "{%0,%1,%2,%3}, {%4,%5,%6,%7}, {%8,%9}, {%0,%1,%2,%3};"
        : "+f"(c[0]), "+f"(c[1]), "+f"(c[2]), "+f"(c[3])
        : "r"(a0), "r"(a1), "r"(a2), "r"(a3), "r"(b0), "r"(b1));
}

__device__ __forceinline__ unsigned packh2(float lo, float hi) {
    __half2 h = __floats2half2_rn(lo, hi);   // .x = lo (low half)
    return *(unsigned*)&h;
}

// ---------------------------------------------------------------------------
// Kernel P1: copy X into out[:,0:1024] + convert X to fp16
// ---------------------------------------------------------------------------
__global__ void prep_x_kernel(const float* __restrict__ X, float* __restrict__ out) {
    const size_t row = blockIdx.x;
    const int e0 = threadIdx.x * 8;
    const float* src = X + row * DIMS + e0;
    float4 v0 = *(const float4*)(src);
    float4 v1 = *(const float4*)(src + 4);
    *(float4*)(out + row * OUTD + e0) = v0;
    *(float4*)(out + row * OUTD + e0 + 4) = v1;

    __half h[8];
    h[0] = __float2half_rn(v0.x); h[1] = __float2half_rn(v0.y);
    h[2] = __float2half_rn(v0.z); h[3] = __float2half_rn(v0.w);
    h[4] = __float2half_rn(v1.x); h[5] = __float2half_rn(v1.y);
    h[6] = __float2half_rn(v1.z); h[7] = __float2half_rn(v1.w);
    *(uint4*)(g_xh + row * DIMS + e0) = *(uint4*)h;
}

// ---------------------------------------------------------------------------
// Kernel P2: W -> W^T [n=256][k=1024] fp16 (cols 0..127 Wk, 128..255 Wv)
// ---------------------------------------------------------------------------
__global__ void prep_w_kernel(const float* __restrict__ Wk, const float* __restrict__ Wv) {
    const int n = blockIdx.x;
    const float* W = (n < KSZ) ? Wk : Wv;
    const int nc = (n < KSZ) ? n : (n - KSZ);
    for (int k = threadIdx.x; k < DIMS; k += blockDim.x)
        g_wth[(size_t)n * DIMS + k] = __float2half_rn(W[(size_t)k * KSZ + nc]);
}

// ---------------------------------------------------------------------------
// Kernel G: KV projection GEMM, fp16 m16n8k16, cp.async double-buffered.
// BM=128, BN=128, BK=64, 256 thr, warps 4m x 2n (warp tile 32x64), 2 CTA/SM.
// grid.y==0 -> keys (fp16 [tok][dim]); grid.y==1 -> vals transposed fp16.
// ---------------------------------------------------------------------------
#define GBM 128
#define GBN 128
#define GBK 64
#define ALD 72                                    // halves per A row (64+8)
#define BLD 72
#define GA_HALVES (GBM * ALD)                     // 9216
#define GB_HALVES (GBN * BLD)                     // 9216
#define GBUF_BYTES ((GA_HALVES + GB_HALVES) * 2)  // 36864
#define GB_OFF (GA_HALVES * 2)                    // 18432
#define GEMM_SMEM_BYTES (2 * GBUF_BYTES)          // 73728

__global__ __launch_bounds__(256, 2) void kv_gemm_f16(
        const float* __restrict__ bk, const float* __restrict__ bv) {
    extern __shared__ char smc[];
    const unsigned sbase = (unsigned)__cvta_generic_to_shared(smc);
    const int tid = threadIdx.x, lane = tid & 31, wid = tid >> 5;
    const int g = lane >> 2, t = lane & 3;
    const int wm = wid & 3, wn = wid >> 2;
    const int m0 = blockIdx.x * GBM;
    const int n0 = blockIdx.y * GBN;   // 0 (keys) or 128 (vals)

    // A tile: 128 rows x 64 halves (8 chunks/row); B tile same shape.
    #define G_LOAD(bb, k0) do {                                               \
        unsigned ab = sbase + (bb) * GBUF_BYTES;                              \
        _Pragma("unroll")                                                     \
        for (int i = 0; i < 4; i++) {                                         \
            int idx = tid + i * 256;                                          \
            int row = idx >> 3, ch = idx & 7;                                 \
            cp16a(ab + (row * ALD + ch * 8) * 2,                              \
                  g_xh + (size_t)(m0 + row) * DIMS + (k0) + ch * 8);          \
            cp16a(ab + GB_OFF + (row * BLD + ch * 8) * 2,                     \
                  g_wth + (size_t)(n0 + row) * DIMS + (k0) + ch * 8);         \
        }                                                                     \
    } while (0)

    float acc[2][8][4];
    #pragma unroll
    for (int mt = 0; mt < 2; mt++)
        #pragma unroll
        for (int nt = 0; nt < 8; nt++)
            #pragma unroll
            for (int i = 0; i < 4; i++) acc[mt][nt][i] = 0.f;

    G_LOAD(0, 0);
    CP_COMMIT();

    const int NK = DIMS / GBK;   // 16
    for (int kk0 = 0; kk0 < NK; kk0++) {
        if (kk0 + 1 < NK) {
            G_LOAD((kk0 + 1) & 1, (kk0 + 1) * GBK);
            CP_COMMIT();
            CP_WAIT(1);
        } else {
            CP_WAIT(0);
        }
        __syncthreads();

        const unsigned* As = (const unsigned*)(smc + (kk0 & 1) * GBUF_BYTES);
        const unsigned* Bs = (const unsigned*)(smc + (kk0 & 1) * GBUF_BYTES + GB_OFF);
        #pragma unroll
        for (int ks = 0; ks < 4; ks++) {
            const int kk = ks * 16 + 2 * t;
            unsigned a[2][4];
            #pragma unroll
            for (int mt = 0; mt < 2; mt++) {
                int r = wm * 32 + mt * 16 + g;
                a[mt][0] = As[(r * ALD + kk) >> 1];
                a[mt][1] = As[((r + 8) * ALD + kk) >> 1];
                a[mt][2] = As[(r * ALD + kk + 8) >> 1];
                a[mt][3] = As[((r + 8) * ALD + kk + 8) >> 1];
            }
            unsigned b[8][2];
            #pragma unroll
            for (int nt = 0; nt < 8; nt++) {
                int n = wn * 64 + nt * 8 + g;
                b[nt][0] = Bs[(n * BLD + kk) >> 1];
                b[nt][1] = Bs[(n * BLD + kk + 8) >> 1];
            }
            #pragma unroll
            for (int mt = 0; mt < 2; mt++)
                #pragma unroll
                for (int nt = 0; nt < 8; nt++)
                    mma_f16(acc[mt][nt], a[mt][0], a[mt][1], a[mt][2], a[mt][3],
                            b[nt][0], b[nt][1]);
        }
        __syncthreads();
    }

    if (blockIdx.y == 0) {
        // keys: fp16 [tok][dim]
        #pragma unroll
        for (int mt = 0; mt < 2; mt++) {
            int row = m0 + wm * 32 + mt * 16 + g;
            #pragma unroll
            for (int nt = 0; nt < 8; nt++) {
                int col = wn * 64 + nt * 8 + 2 * t;
                float b0 = bk[col], b1 = bk[col + 1];
                *(unsigned*)&g_keys_h[(size_t)row * KSZ + col] =
                    packh2(acc[mt][nt][0] + b0, acc[mt][nt][1] + b1);
                *(unsigned*)&g_keys_h[(size_t)(row + 8) * KSZ + col] =
                    packh2(acc[mt][nt][2] + b0, acc[mt][nt][3] + b1);
            }
        }
    } else {
        // vals: transpose via smem -> fp16 [b][dim][tok]
        __half* Vst = (__half*)smc;   // [col 128][row 128] ld 136
        #pragma unroll
        for (int mt = 0; mt < 2; mt++) {
            int r = wm * 32 + mt * 16 + g;
            #pragma unroll
            for (int nt = 0; nt < 8; nt++) {
                int col = wn * 64 + nt * 8 + 2 * t;
                float b0 = bv[col], b1 = bv[col + 1];
                Vst[(col    ) * 136 + r    ] = __float2half_rn(acc[mt][nt][0] + b0);
                Vst[(col + 1) * 136 + r    ] = __float2half_rn(acc[mt][nt][1] + b1);
                Vst[(col    ) * 136 + r + 8] = __float2half_rn(acc[mt][nt][2] + b0);
                Vst[(col + 1) * 136 + r + 8] = __float2half_rn(acc[mt][nt][3] + b1);
            }
        }
        __syncthreads();
        const int bb = m0 >> 11;          // batch
        const int tloc = m0 & 2047;       // token offset within batch
        #pragma unroll
        for (int i = 0; i < 8; i++) {
            int idx = tid + i * 256;      // 128 cols x 16 chunks
            int col = idx >> 4, ch = idx & 15;
            uint4 v = *(uint4*)&Vst[col * 136 + ch * 8];
            *(uint4*)&g_valsT_h[((size_t)bb * KSZ + col) * SEQ + tloc + ch * 8] = v;
        }
    }
}

// ---------------------------------------------------------------------------
// Kernel A: causal flash attention, fp16 mma, dual warp-group (named bars).
// AQ=AK=64, Q in regs (32), K [key][dim] fp16, V^T [dim][key] fp16, dbl-buf.
// ---------------------------------------------------------------------------
#define AQ 64
#define AK 64
#define KLD 136                      // halves per K row (128+8)
#define VLD 72                       // halves per V^T row (64+8)
#define PLD 72
#define NQT (SEQ / AQ)               // 32
#define K_TILE_H (AK * KLD)          // 8704
#define VT_TILE_H (KSZ * VLD)        // 9216
#define GOFF_K0 0
#define GOFF_K1 (K_TILE_H)
#define GOFF_VT0 (2 * K_TILE_H)
#define GOFF_VT1 (2 * K_TILE_H + VT_TILE_H)
#define GOFF_P  (2 * K_TILE_H + 2 * VT_TILE_H)      // 35840
#define GRP_H (GOFF_P + AQ * PLD)                   // 40448 halves
#define ATTN_SMEM_BYTES (2 * GRP_H * 2)             // 161792

__global__ __launch_bounds__(256, 1) void attn_kernel(float* __restrict__ out) {
    extern __shared__ char smc[];
    const int tid = threadIdx.x, lane = tid & 31, wid = tid >> 5;
    const int g = lane >> 2, t = lane & 3;
    const int grp = wid >> 2, wg = wid & 3, gt = tid & 127;
    const int barid = grp + 1;
    #define GBAR() asm volatile("bar.sync %0, 128;" :: "r"(barid))

    char* gbase = smc + grp * GRP_H * 2;
    const unsigned sgb = (unsigned)__cvta_generic_to_shared(gbase);
    const unsigned* S32 = (const unsigned*)gbase;

    const int pairIdx = blockIdx.x;          // 0..15
    const int bq = blockIdx.y;               // batch
    const int qt = grp ? (NQT - 1 - pairIdx) : pairIdx;
    const int qbase = qt * AQ;
    const int nkt = qt + 1;
    const __half* keys = g_keys_h + (size_t)bq * SEQ * KSZ;
    const __half* valsT = g_valsT_h + (size_t)bq * KSZ * SEQ;
    const float scale = 0.08838834764831843f;   // 1/sqrt(128)

    // K tile: 64 rows x 128 halves = 1024 chunks (row = idx>>4, ch = idx&15)
    // VT tile: 128 rows x 64 halves = 1024 chunks (row = idx>>3, ch = idx&7)
    #define LOAD_KV(buf, kbase) do {                                          \
        _Pragma("unroll")                                                     \
        for (int i = 0; i < 8; i++) {                                         \
            int idx = gt + i * 128;                                           \
            int row = idx >> 4, ch = idx & 15;                                \
            cp16a(sgb + ((buf ? GOFF_K1 : GOFF_K0) + row * KLD + ch * 8) * 2, \
                  keys + (size_t)((kbase) + row) * KSZ + ch * 8);             \
        }                                                                     \
        _Pragma("unroll")                                                     \
        for (int i = 0; i < 8; i++) {                                         \
            int idx = gt + i * 128;                                           \
            int row = idx >> 3, ch = idx & 7;                                 \
            cp16a(sgb + ((buf ? GOFF_VT1 : GOFF_VT0) + row * VLD + ch * 8) * 2, \
                  valsT + (size_t)row * SEQ + (kbase) + ch * 8);              \
        }                                                                     \
    } while (0)

    // stage Q through K0 region (64 rows x 128 halves = 1024 chunks)
    #pragma unroll
    for (int i = 0; i < 8; i++) {
        int idx = gt + i * 128;
        int row = idx >> 4, ch = idx & 15;
        cp16a(sgb + (row * KLD + ch * 8) * 2,
              keys + (size_t)(qbase + row) * KSZ + ch * 8);
    }
    CP_COMMIT();
    CP_WAIT(0);
    GBAR();

    unsigned qa[8][4];
    {
        const int r0 = wg * 16 + g;
        #pragma unroll
        for (int ks = 0; ks < 8; ks++) {
            const int kk = ks * 16 + 2 * t;
            qa[ks][0] = S32[(r0 * KLD + kk) >> 1];
            qa[ks][1] = S32[((r0 + 8) * KLD + kk) >> 1];
            qa[ks][2] = S32[(r0 * KLD + kk + 8) >> 1];
            qa[ks][3] = S32[((r0 + 8) * KLD + kk + 8) >> 1];
        }
    }
    GBAR();

    LOAD_KV(0, 0);
    CP_COMMIT();

    float O[16][4];
    #pragma unroll
    for (int nt = 0; nt < 16; nt++)
        #pragma unroll
        for (int i = 0; i < 4; i++) O[nt][i] = 0.f;
    float mrow[2] = {-1e30f, -1e30f};
    float lrow[2] = {0.f, 0.f};

    for (int j = 0; j < nkt; j++) {
        if (j + 1 < nkt) {
            LOAD_KV((j + 1) & 1, (j + 1) * AK);
            CP_COMMIT();
            CP_WAIT(1);
        } else {
            CP_WAIT(0);
        }
        GBAR();

        const unsigned* Ks = S32 + ((j & 1) ? GOFF_K1 : GOFF_K0) / 2;
        const unsigned* VTs = S32 + ((j & 1) ? GOFF_VT1 : GOFF_VT0) / 2;
        unsigned* Ps32 = (unsigned*)(gbase + GOFF_P * 2);
        const int kbase = j * AK;

        // S = Q @ K^T : 16 rows x 64 keys
        float s[8][4];
        #pragma unroll
        for (int nt = 0; nt < 8; nt++)
            #pragma unroll
            for (int i = 0; i < 4; i++) s[nt][i] = 0.f;

        #pragma unroll
        for (int ks = 0; ks < 8; ks++) {
            const int kk = ks * 16 + 2 * t;
            #pragma unroll
            for (int nt = 0; nt < 8; nt++) {
                int n = nt * 8 + g;
                mma_f16(s[nt], qa[ks][0], qa[ks][1], qa[ks][2], qa[ks][3],
                        Ks[(n * KLD + kk) >> 1], Ks[(n * KLD + kk + 8) >> 1]);
            }
        }

        #pragma unroll
        for (int nt = 0; nt < 8; nt++)
            #pragma unroll
            for (int i = 0; i < 4; i++) s[nt][i] *= scale;

        // causal mask on diagonal tile only (AK==AQ aligned), exactly -100
        if (j == nkt - 1) {
            const int qg0 = qbase + wg * 16 + g;
            const int qg1 = qg0 + 8;
            #pragma unroll
            for (int nt = 0; nt < 8; nt++) {
                int kg = kbase + nt * 8 + 2 * t;
                if (kg     > qg0) s[nt][0] = -100.0f;
                if (kg + 1 > qg0) s[nt][1] = -100.0f;
                if (kg     > qg1) s[nt][2] = -100.0f;
                if (kg + 1 > qg1) s[nt][3] = -100.0f;
            }
        }

        // online softmax (rows in quads: shfl xor 1,2)
        #pragma unroll
        for (int h = 0; h < 2; h++) {
            float mx = -1e30f;
            #pragma unroll
            for (int nt = 0; nt < 8; nt++)
                mx = fmaxf(mx, fmaxf(s[nt][2 * h], s[nt][2 * h + 1]));
            mx = fmaxf(mx, __shfl_xor_sync(0xffffffffu, mx, 1));
            mx = fmaxf(mx, __shfl_xor_sync(0xffffffffu, mx, 2));
            float mnew = fmaxf(mrow[h], mx);
            float alpha = __expf(mrow[h] - mnew);
            mrow[h] = mnew;
            float sum = 0.f;
            #pragma unroll
            for (int nt = 0; nt < 8; nt++) {
                float p0 = __expf(s[nt][2 * h] - mnew);
                float p1 = __expf(s[nt][2 * h + 1] - mnew);
                s[nt][2 * h] = p0; s[nt][2 * h + 1] = p1;
                sum += p0 + p1;
            }
            sum += __shfl_xor_sync(0xffffffffu, sum, 1);
            sum += __shfl_xor_sync(0xffffffffu, sum, 2);
            lrow[h] = lrow[h] * alpha + sum;
            #pragma unroll
            for (int nt = 0; nt < 16; nt++) {
                O[nt][2 * h]     *= alpha;
                O[nt][2 * h + 1] *= alpha;
            }
        }

        // stage P as fp16 pairs in per-warp smem rows
        {
            const int r = wg * 16 + g;
            #pragma unroll
            for (int nt = 0; nt < 8; nt++) {
                int col = nt * 8 + 2 * t;
                Ps32[(r * PLD + col) >> 1]       = packh2(s[nt][0], s[nt][1]);
                Ps32[((r + 8) * PLD + col) >> 1] = packh2(s[nt][2], s[nt][3]);
            }
        }
        __syncwarp();

        // O += P @ V  (V^T layout: b-pairs along key dim)
        #pragma unroll
        for (int ks = 0; ks < 4; ks++) {
            const int kk = ks * 16 + 2 * t;
            const int r = wg * 16 + g;
            unsigned a0 = Ps32[(r * PLD + kk) >> 1];
            unsigned a1 = Ps32[((r + 8) * PLD + kk) >> 1];
            unsigned a2 = Ps32[(r * PLD + kk + 8) >> 1];
            unsigned a3 = Ps32[((r + 8) * PLD + kk + 8) >> 1];
            #pragma unroll
            for (int nt = 0; nt < 16; nt++) {
                int n = nt * 8 + g;
                mma_f16(O[nt], a0, a1, a2, a3,
                        VTs[(n * VLD + kk) >> 1], VTs[(n * VLD + kk + 8) >> 1]);
            }
        }
        GBAR();
    }

    // epilogue: normalize, write out[:, 1024:1152]
    {
        float inv0 = 1.0f / lrow[0];
        float inv1 = 1.0f / lrow[1];
        int qg0 = qbase + wg * 16 + g;
        size_t base0 = ((size_t)bq * SEQ + qg0) * OUTD + DIMS;
        size_t base1 = base0 + (size_t)8 * OUTD;
        #pragma unroll
        for (int nt = 0; nt < 16; nt++) {
            int c = nt * 8 + 2 * t;
            *(float2*)(out + base0 + c) = make_float2(O[nt][0] * inv0, O[nt][1] * inv0);
            *(float2*)(out + base1 + c) = make_float2(O[nt][2] * inv1, O[nt][3] * inv1);
        }
    }
}

// ---------------------------------------------------------------------------
extern "C" void kernel_launch(void* const* d_in, const int* in_sizes, int n_in,
                              void* d_out, int out_size) {
    const float* X  = (const float*)d_in[0];
    const float* Wk = (const float*)d_in[1];
    const float* bk = (const float*)d_in[2];
    const float* Wv = (const float*)d_in[3];
    const float* bv = (const float*)d_in[4];
    float* out = (float*)d_out;

    prep_x_kernel<<<M_TOTAL, 128>>>(X, out);
    prep_w_kernel<<<2 * KSZ, 256>>>(Wk, Wv);

    cudaFuncSetAttribute(kv_gemm_f16, cudaFuncAttributeMaxDynamicSharedMemorySize,
                         GEMM_SMEM_BYTES);
    kv_gemm_f16<<<dim3(M_TOTAL / GBM, 2), 256, GEMM_SMEM_BYTES>>>(bk, bv);

    cudaFuncSetAttribute(attn_kernel, cudaFuncAttributeMaxDynamicSharedMemorySize,
                         ATTN_SMEM_BYTES);
    attn_kernel<<<dim3(NQT / 2, BATCH), 256, ATTN_SMEM_BYTES>>>(out);
}

// round 10
// speedup vs baseline: 2.8649x; 1.0997x over previous
#include <cuda_runtime.h>
#include <cuda_fp16.h>
#include <math.h>

#define DIMS 1024
#define KSZ  128
#define SEQ  2048
#define BATCH 8
#define M_TOTAL (BATCH*SEQ)     // 16384
#define OUTD (DIMS + KSZ)       // 1152

// scratch (allocation-free rule: __device__ globals)
__device__ __half g_xh[M_TOTAL * DIMS];                 // X fp16
__device__ __half g_wth[2 * KSZ * DIMS];                // [n=256][k=1024] W^T fp16
__device__ __half g_keys_h[M_TOTAL * KSZ];              // keys fp16 [tok][dim]
__device__ __half g_valsT_h[(size_t)BATCH * KSZ * SEQ]; // vals^T fp16 [b][dim][tok]

// ---------------------------------------------------------------------------
// helpers
// ---------------------------------------------------------------------------
__device__ __forceinline__ void cp16a(unsigned daddr, const void* src) {
    asm volatile("cp.async.cg.shared.global [%0], [%1], 16;" :: "r"(daddr), "l"(src));
}
#define CP_COMMIT() asm volatile("cp.async.commit_group;")
#define CP_WAIT(n)  asm volatile("cp.async.wait_group %0;" :: "n"(n))

__device__ __forceinline__ void mma_f16(float* c,
        unsigned a0, unsigned a1, unsigned a2, unsigned a3,
        unsigned b0, unsigned b1) {
    asm volatile(
        "mma.sync.aligned.m16n8k16.row.col.f32.f16.f16.f32 "
        "{%0,%1,%2,%3}, {%4,%5,%6,%7}, {%8,%9}, {%0,%1,%2,%3};"
        : "+f"(c[0]), "+f"(c[1]), "+f"(c[2]), "+f"(c[3])
        : "r"(a0), "r"(a1), "r"(a2), "r"(a3), "r"(b0), "r"(b1));
}

__device__ __forceinline__ void ldmat_x4(unsigned& r0, unsigned& r1,
                                         unsigned& r2, unsigned& r3, unsigned saddr) {
    asm volatile("ldmatrix.sync.aligned.m8n8.x4.shared.b16 {%0,%1,%2,%3}, [%4];"
        : "=r"(r0), "=r"(r1), "=r"(r2), "=r"(r3) : "r"(saddr));
}

__device__ __forceinline__ unsigned packh2(float lo, float hi) {
    __half2 h = __floats2half2_rn(lo, hi);
    return *(unsigned*)&h;
}

// ldmatrix per-thread row-address offsets (in halves):
//  a-type (matrices: [m0-7,klo][m8-15,klo][m0-7,khi][m8-15,khi]):
//    row = ((lane>>3)&1)*8 + (lane&7),  kofs = ((lane>>4)&1)*8
//  b-type (matrices: [n0-7,klo][n0-7,khi][n8-15,klo][n8-15,khi]):
//    row = ((lane>>4)&1)*8 + (lane&7),  kofs = ((lane>>3)&1)*8
#define LDM_A_ROW(lane) ((((lane) >> 3) & 1) * 8 + ((lane) & 7))
#define LDM_A_K(lane)   ((((lane) >> 4) & 1) * 8)
#define LDM_B_ROW(lane) ((((lane) >> 4) & 1) * 8 + ((lane) & 7))
#define LDM_B_K(lane)   ((((lane) >> 3) & 1) * 8)

// ---------------------------------------------------------------------------
// Kernel P1: copy X into out[:,0:1024] + convert X to fp16
// ---------------------------------------------------------------------------
__global__ void prep_x_kernel(const float* __restrict__ X, float* __restrict__ out) {
    const size_t row = blockIdx.x;
    const int e0 = threadIdx.x * 8;
    const float* src = X + row * DIMS + e0;
    float4 v0 = *(const float4*)(src);
    float4 v1 = *(const float4*)(src + 4);
    *(float4*)(out + row * OUTD + e0) = v0;
    *(float4*)(out + row * OUTD + e0 + 4) = v1;

    __half h[8];
    h[0] = __float2half_rn(v0.x); h[1] = __float2half_rn(v0.y);
    h[2] = __float2half_rn(v0.z); h[3] = __float2half_rn(v0.w);
    h[4] = __float2half_rn(v1.x); h[5] = __float2half_rn(v1.y);
    h[6] = __float2half_rn(v1.z); h[7] = __float2half_rn(v1.w);
    *(uint4*)(g_xh + row * DIMS + e0) = *(uint4*)h;
}

// ---------------------------------------------------------------------------
// Kernel P2: W -> W^T [n=256][k=1024] fp16
// ---------------------------------------------------------------------------
__global__ void prep_w_kernel(const float* __restrict__ Wk, const float* __restrict__ Wv) {
    const int n = blockIdx.x;
    const float* W = (n < KSZ) ? Wk : Wv;
    const int nc = (n < KSZ) ? n : (n - KSZ);
    for (int k = threadIdx.x; k < DIMS; k += blockDim.x)
        g_wth[(size_t)n * DIMS + k] = __float2half_rn(W[(size_t)k * KSZ + nc]);
}

// ---------------------------------------------------------------------------
// Kernel G: fused KV projection GEMM. BM=128, BN=256, BK=64, 512 threads
// (16 warps 4m x 4n, warp tile 32x64), ldmatrix fragments, double buffered.
// n 0..127 -> keys [tok][dim]; n 128..255 -> vals transposed [b][dim][tok].
// ---------------------------------------------------------------------------
#define GBK 64
#define ALD 72
#define BLD 72
#define GA_H (128 * ALD)                          // 9216
#define GB_H (256 * BLD)                          // 18432
#define GB_OFF (GA_H * 2)
#define GBUF_BYTES ((GA_H + GB_H) * 2)            // 55296
#define GEMM_SMEM_BYTES (2 * GBUF_BYTES)          // 110592

__global__ __launch_bounds__(512, 1) void kv_gemm_f16(
        const float* __restrict__ bk, const float* __restrict__ bv) {
    extern __shared__ char smc[];
    const unsigned sbase = (unsigned)__cvta_generic_to_shared(smc);
    const int tid = threadIdx.x, lane = tid & 31, wid = tid >> 5;
    const int g = lane >> 2, t = lane & 3;
    const int wm = wid & 3, wn = wid >> 2;        // 4 x 4 warps
    const int m0 = blockIdx.x * 128;

    const int raA = LDM_A_ROW(lane), kaA = LDM_A_K(lane);
    const int rbB = LDM_B_ROW(lane), kbB = LDM_B_K(lane);

    #define G_LOAD(bb, k0) do {                                               \
        unsigned ab = sbase + (bb) * GBUF_BYTES;                              \
        _Pragma("unroll")                                                     \
        for (int i = 0; i < 2; i++) {                                         \
            int idx = tid + i * 512;                                          \
            int row = idx >> 3, ch = idx & 7;                                 \
            cp16a(ab + (row * ALD + ch * 8) * 2,                              \
                  g_xh + (size_t)(m0 + row) * DIMS + (k0) + ch * 8);          \
        }                                                                     \
        _Pragma("unroll")                                                     \
        for (int i = 0; i < 4; i++) {                                         \
            int idx = tid + i * 512;                                          \
            int row = idx >> 3, ch = idx & 7;                                 \
            cp16a(ab + GB_OFF + (row * BLD + ch * 8) * 2,                     \
                  g_wth + (size_t)row * DIMS + (k0) + ch * 8);                \
        }                                                                     \
    } while (0)

    float acc[2][8][4];
    #pragma unroll
    for (int mt = 0; mt < 2; mt++)
        #pragma unroll
        for (int nt = 0; nt < 8; nt++)
            #pragma unroll
            for (int i = 0; i < 4; i++) acc[mt][nt][i] = 0.f;

    G_LOAD(0, 0);
    CP_COMMIT();

    const int NK = DIMS / GBK;   // 16
    for (int kk0 = 0; kk0 < NK; kk0++) {
        if (kk0 + 1 < NK) {
            G_LOAD((kk0 + 1) & 1, (kk0 + 1) * GBK);
            CP_COMMIT();
            CP_WAIT(1);
        } else {
            CP_WAIT(0);
        }
        __syncthreads();

        const unsigned ab = sbase + (kk0 & 1) * GBUF_BYTES;
        const unsigned aW = ab + ((wm * 32 + raA) * ALD + kaA) * 2;
        const unsigned bW = ab + GB_OFF + ((wn * 64 + rbB) * BLD + kbB) * 2;
        #pragma unroll
        for (int ks = 0; ks < 4; ks++) {
            const int kk = ks * 16;
            unsigned a[2][4];
            #pragma unroll
            for (int mt = 0; mt < 2; mt++)
                ldmat_x4(a[mt][0], a[mt][1], a[mt][2], a[mt][3],
                         aW + (mt * 16 * ALD + kk) * 2);
            #pragma unroll
            for (int ntp = 0; ntp < 4; ntp++) {
                unsigned b0a, b1a, b0b, b1b;
                ldmat_x4(b0a, b1a, b0b, b1b, bW + (ntp * 16 * BLD + kk) * 2);
                #pragma unroll
                for (int mt = 0; mt < 2; mt++) {
                    mma_f16(acc[mt][2 * ntp],
                            a[mt][0], a[mt][1], a[mt][2], a[mt][3], b0a, b1a);
                    mma_f16(acc[mt][2 * ntp + 1],
                            a[mt][0], a[mt][1], a[mt][2], a[mt][3], b0b, b1b);
                }
            }
        }
        __syncthreads();
    }

    if (wn < 2) {
        // keys: fp16 [tok][dim]
        #pragma unroll
        for (int mt = 0; mt < 2; mt++) {
            int row = m0 + wm * 32 + mt * 16 + g;
            #pragma unroll
            for (int nt = 0; nt < 8; nt++) {
                int col = wn * 64 + nt * 8 + 2 * t;
                float b0 = bk[col], b1 = bk[col + 1];
                *(unsigned*)&g_keys_h[(size_t)row * KSZ + col] =
                    packh2(acc[mt][nt][0] + b0, acc[mt][nt][1] + b1);
                *(unsigned*)&g_keys_h[(size_t)(row + 8) * KSZ + col] =
                    packh2(acc[mt][nt][2] + b0, acc[mt][nt][3] + b1);
            }
        }
        __syncthreads();   // match vals warps
    } else {
        // vals: transpose via smem -> fp16 [b][dim][tok]
        __half* Vst = (__half*)smc;   // [dim 128][tok 128+8]
        #pragma unroll
        for (int mt = 0; mt < 2; mt++) {
            int r = wm * 32 + mt * 16 + g;
            #pragma unroll
            for (int nt = 0; nt < 8; nt++) {
                int dcol = (wn - 2) * 64 + nt * 8 + 2 * t;
                float b0 = bv[dcol], b1 = bv[dcol + 1];
                Vst[(dcol    ) * 136 + r    ] = __float2half_rn(acc[mt][nt][0] + b0);
                Vst[(dcol + 1) * 136 + r    ] = __float2half_rn(acc[mt][nt][1] + b1);
                Vst[(dcol    ) * 136 + r + 8] = __float2half_rn(acc[mt][nt][2] + b0);
                Vst[(dcol + 1) * 136 + r + 8] = __float2half_rn(acc[mt][nt][3] + b1);
            }
        }
        __syncthreads();
    }
    // cooperative global write of vals^T (all 512 threads)
    {
        __half* Vst = (__half*)smc;
        const int bb = m0 >> 11;
        const int tloc = m0 & 2047;
        #pragma unroll
        for (int i = 0; i < 4; i++) {
            int idx = tid + i * 512;      // 128 dims x 16 chunks
            int col = idx >> 4, ch = idx & 15;
            uint4 v = *(uint4*)&Vst[col * 136 + ch * 8];
            *(uint4*)&g_valsT_h[((size_t)bb * KSZ + col) * SEQ + tloc + ch * 8] = v;
        }
    }
}

// ---------------------------------------------------------------------------
// Kernel A: causal flash attention, fp16 mma + ldmatrix, dual warp-group.
// AQ=AK=64, Q in regs, K [key][dim], V^T [dim][key], double buffered.
// ---------------------------------------------------------------------------
#define AQ 64
#define AK 64
#define KLD 136
#define VLD 72
#define PLD 72
#define NQT (SEQ / AQ)               // 32
#define K_TILE_H (AK * KLD)          // 8704
#define VT_TILE_H (KSZ * VLD)        // 9216
#define GOFF_K0 0
#define GOFF_K1 (K_TILE_H)
#define GOFF_VT0 (2 * K_TILE_H)
#define GOFF_VT1 (2 * K_TILE_H + VT_TILE_H)
#define GOFF_P  (2 * K_TILE_H + 2 * VT_TILE_H)
#define GRP_H (GOFF_P + AQ * PLD)
#define ATTN_SMEM_BYTES (2 * GRP_H * 2)             // 161792

__global__ __launch_bounds__(256, 1) void attn_kernel(float* __restrict__ out) {
    extern __shared__ char smc[];
    const int tid = threadIdx.x, lane = tid & 31, wid = tid >> 5;
    const int g = lane >> 2, t = lane & 3;
    const int grp = wid >> 2, wg = wid & 3, gt = tid & 127;
    const int barid = grp + 1;
    #define GBAR() asm volatile("bar.sync %0, 128;" :: "r"(barid))

    char* gbase = smc + grp * GRP_H * 2;
    const unsigned sgb = (unsigned)__cvta_generic_to_shared(gbase);

    const int pairIdx = blockIdx.x;
    const int bq = blockIdx.y;
    const int qt = grp ? (NQT - 1 - pairIdx) : pairIdx;
    const int qbase = qt * AQ;
    const int nkt = qt + 1;
    const __half* keys = g_keys_h + (size_t)bq * SEQ * KSZ;
    const __half* valsT = g_valsT_h + (size_t)bq * KSZ * SEQ;
    const float scale = 0.08838834764831843f;   // 1/sqrt(128)

    const int raA = LDM_A_ROW(lane), kaA = LDM_A_K(lane);
    const int rbB = LDM_B_ROW(lane), kbB = LDM_B_K(lane);
    const int rw = wg * 16;

    #define LOAD_KV(buf, kbase) do {                                          \
        _Pragma("unroll")                                                     \
        for (int i = 0; i < 8; i++) {                                         \
            int idx = gt + i * 128;                                           \
            int row = idx >> 4, ch = idx & 15;                                \
            cp16a(sgb + ((buf ? GOFF_K1 : GOFF_K0) + row * KLD + ch * 8) * 2, \
                  keys + (size_t)((kbase) + row) * KSZ + ch * 8);             \
        }                                                                     \
        _Pragma("unroll")                                                     \
        for (int i = 0; i < 8; i++) {                                         \
            int idx = gt + i * 128;                                           \
            int row = idx >> 3, ch = idx & 7;                                 \
            cp16a(sgb + ((buf ? GOFF_VT1 : GOFF_VT0) + row * VLD + ch * 8) * 2, \
                  valsT + (size_t)row * SEQ + (kbase) + ch * 8);              \
        }                                                                     \
    } while (0)

    // stage Q through K0 region
    #pragma unroll
    for (int i = 0; i < 8; i++) {
        int idx = gt + i * 128;
        int row = idx >> 4, ch = idx & 15;
        cp16a(sgb + (row * KLD + ch * 8) * 2,
              keys + (size_t)(qbase + row) * KSZ + ch * 8);
    }
    CP_COMMIT();
    CP_WAIT(0);
    GBAR();

    // Q fragments via ldmatrix (a-type)
    unsigned qa[8][4];
    {
        const unsigned qW = sgb + ((rw + raA) * KLD + kaA) * 2;
        #pragma unroll
        for (int ks = 0; ks < 8; ks++)
            ldmat_x4(qa[ks][0], qa[ks][1], qa[ks][2], qa[ks][3], qW + ks * 32);
    }
    GBAR();

    LOAD_KV(0, 0);
    CP_COMMIT();

    float O[16][4];
    #pragma unroll
    for (int nt = 0; nt < 16; nt++)
        #pragma unroll
        for (int i = 0; i < 4; i++) O[nt][i] = 0.f;
    float mrow[2] = {-1e30f, -1e30f};
    float lrow[2] = {0.f, 0.f};

    for (int j = 0; j < nkt; j++) {
        if (j + 1 < nkt) {
            LOAD_KV((j + 1) & 1, (j + 1) * AK);
            CP_COMMIT();
            CP_WAIT(1);
        } else {
            CP_WAIT(0);
        }
        GBAR();

        const unsigned kW = sgb + ((j & 1) ? GOFF_K1 : GOFF_K0) * 2
                          + (rbB * KLD + kbB) * 2;
        const unsigned vW = sgb + ((j & 1) ? GOFF_VT1 : GOFF_VT0) * 2
                          + (rbB * VLD + kbB) * 2;
        unsigned* Ps32 = (unsigned*)(gbase + GOFF_P * 2);
        const int kbase = j * AK;

        // S = Q @ K^T : 16 rows x 64 keys
        float s[8][4];
        #pragma unroll
        for (int nt = 0; nt < 8; nt++)
            #pragma unroll
            for (int i = 0; i < 4; i++) s[nt][i] = 0.f;

        #pragma unroll
        for (int ks = 0; ks < 8; ks++) {
            #pragma unroll
            for (int ntp = 0; ntp < 4; ntp++) {
                unsigned b0a, b1a, b0b, b1b;
                ldmat_x4(b0a, b1a, b0b, b1b, kW + (ntp * 16 * KLD + ks * 16) * 2);
                mma_f16(s[2 * ntp],
                        qa[ks][0], qa[ks][1], qa[ks][2], qa[ks][3], b0a, b1a);
                mma_f16(s[2 * ntp + 1],
                        qa[ks][0], qa[ks][1], qa[ks][2], qa[ks][3], b0b, b1b);
            }
        }

        #pragma unroll
        for (int nt = 0; nt < 8; nt++)
            #pragma unroll
            for (int i = 0; i < 4; i++) s[nt][i] *= scale;

        // causal mask on diagonal tile only, exactly -100
        if (j == nkt - 1) {
            const int qg0 = qbase + rw + g;
            const int qg1 = qg0 + 8;
            #pragma unroll
            for (int nt = 0; nt < 8; nt++) {
                int kg = kbase + nt * 8 + 2 * t;
                if (kg     > qg0) s[nt][0] = -100.0f;
                if (kg + 1 > qg0) s[nt][1] = -100.0f;
                if (kg     > qg1) s[nt][2] = -100.0f;
                if (kg + 1 > qg1) s[nt][3] = -100.0f;
            }
        }

        // online softmax; O-rescale only when the running max changes
        #pragma unroll
        for (int h = 0; h < 2; h++) {
            float mx = -1e30f;
            #pragma unroll
            for (int nt = 0; nt < 8; nt++)
                mx = fmaxf(mx, fmaxf(s[nt][2 * h], s[nt][2 * h + 1]));
            mx = fmaxf(mx, __shfl_xor_sync(0xffffffffu, mx, 1));
            mx = fmaxf(mx, __shfl_xor_sync(0xffffffffu, mx, 2));
            if (mx > mrow[h]) {
                float alpha = __expf(mrow[h] - mx);
                mrow[h] = mx;
                lrow[h] *= alpha;
                #pragma unroll
                for (int nt = 0; nt < 16; nt++) {
                    O[nt][2 * h]     *= alpha;
                    O[nt][2 * h + 1] *= alpha;
                }
            }
            float m = mrow[h];
            float sum = 0.f;
            #pragma unroll
            for (int nt = 0; nt < 8; nt++) {
                float p0 = __expf(s[nt][2 * h] - m);
                float p1 = __expf(s[nt][2 * h + 1] - m);
                s[nt][2 * h] = p0; s[nt][2 * h + 1] = p1;
                sum += p0 + p1;
            }
            sum += __shfl_xor_sync(0xffffffffu, sum, 1);
            sum += __shfl_xor_sync(0xffffffffu, sum, 2);
            lrow[h] += sum;
        }

        // stage P as fp16 pairs in per-warp smem rows
        {
            #pragma unroll
            for (int nt = 0; nt < 8; nt++) {
                int col = nt * 8 + 2 * t;
                Ps32[((rw + g) * PLD + col) >> 1]     = packh2(s[nt][0], s[nt][1]);
                Ps32[((rw + g + 8) * PLD + col) >> 1] = packh2(s[nt][2], s[nt][3]);
            }
        }
        __syncwarp();

        // O += P @ V
        const unsigned pW = sgb + GOFF_P * 2 + ((rw + raA) * PLD + kaA) * 2;
        #pragma unroll
        for (int ks = 0; ks < 4; ks++) {
            unsigned pa0, pa1, pa2, pa3;
            ldmat_x4(pa0, pa1, pa2, pa3, pW + ks * 32);
            #pragma unroll
            for (int ntp = 0; ntp < 8; ntp++) {
                unsigned b0a, b1a, b0b, b1b;
                ldmat_x4(b0a, b1a, b0b, b1b, vW + (ntp * 16 * VLD + ks * 16) * 2);
                mma_f16(O[2 * ntp], pa0, pa1, pa2, pa3, b0a, b1a);
                mma_f16(O[2 * ntp + 1], pa0, pa1, pa2, pa3, b0b, b1b);
            }
        }
        GBAR();
    }

    // epilogue: normalize, write out[:, 1024:1152]
    {
        float inv0 = 1.0f / lrow[0];
        float inv1 = 1.0f / lrow[1];
        int qg0 = qbase + rw + g;
        size_t base0 = ((size_t)bq * SEQ + qg0) * OUTD + DIMS;
        size_t base1 = base0 + (size_t)8 * OUTD;
        #pragma unroll
        for (int nt = 0; nt < 16; nt++) {
            int c = nt * 8 + 2 * t;
            *(float2*)(out + base0 + c) = make_float2(O[nt][0] * inv0, O[nt][1] * inv0);
            *(float2*)(out + base1 + c) = make_float2(O[nt][2] * inv1, O[nt][3] * inv1);
        }
    }
}

// ---------------------------------------------------------------------------
extern "C" void kernel_launch(void* const* d_in, const int* in_sizes, int n_in,
                              void* d_out, int out_size) {
    const float* X  = (const float*)d_in[0];
    const float* Wk = (const float*)d_in[1];
    const float* bk = (const float*)d_in[2];
    const float* Wv = (const float*)d_in[3];
    const float* bv = (const float*)d_in[4];
    float* out = (float*)d_out;

    prep_x_kernel<<<M_TOTAL, 128>>>(X, out);
    prep_w_kernel<<<2 * KSZ, 256>>>(Wk, Wv);

    cudaFuncSetAttribute(kv_gemm_f16, cudaFuncAttributeMaxDynamicSharedMemorySize,
                         GEMM_SMEM_BYTES);
    kv_gemm_f16<<<M_TOTAL / 128, 512, GEMM_SMEM_BYTES>>>(bk, bv);

    cudaFuncSetAttribute(attn_kernel, cudaFuncAttributeMaxDynamicSharedMemorySize,
                         ATTN_SMEM_BYTES);
    attn_kernel<<<dim3(NQT / 2, BATCH), 256, ATTN_SMEM_BYTES>>>(out);
}

// round 11
// speedup vs baseline: 2.8709x; 1.0021x over previous
#include <cuda_runtime.h>
#include <cuda_fp16.h>
#include <math.h>

#define DIMS 1024
#define KSZ  128
#define SEQ  2048
#define BATCH 8
#define M_TOTAL (BATCH*SEQ)     // 16384
#define OUTD (DIMS + KSZ)       // 1152

// scratch (allocation-free rule: __device__ globals)
__device__ __half g_wth[2 * KSZ * DIMS];                // [n=256][k=1024] W^T fp16
__device__ __half g_keys_h[M_TOTAL * KSZ];              // keys fp16 [tok][dim]
__device__ __half g_valsT_h[(size_t)BATCH * KSZ * SEQ]; // vals^T fp16 [b][dim][tok]

// ---------------------------------------------------------------------------
// helpers
// ---------------------------------------------------------------------------
__device__ __forceinline__ void cp16a(unsigned daddr, const void* src) {
    asm volatile("cp.async.cg.shared.global [%0], [%1], 16;" :: "r"(daddr), "l"(src));
}
#define CP_COMMIT() asm volatile("cp.async.commit_group;")
#define CP_WAIT(n)  asm volatile("cp.async.wait_group %0;" :: "n"(n))

__device__ __forceinline__ void mma_f16(float* c,
        unsigned a0, unsigned a1, unsigned a2, unsigned a3,
        unsigned b0, unsigned b1) {
    asm volatile(
        "mma.sync.aligned.m16n8k16.row.col.f32.f16.f16.f32 "
        "{%0,%1,%2,%3}, {%4,%5,%6,%7}, {%8,%9}, {%0,%1,%2,%3};"
        : "+f"(c[0]), "+f"(c[1]), "+f"(c[2]), "+f"(c[3])
        : "r"(a0), "r"(a1), "r"(a2), "r"(a3), "r"(b0), "r"(b1));
}

__device__ __forceinline__ void ldmat_x4(unsigned& r0, unsigned& r1,
                                         unsigned& r2, unsigned& r3, unsigned saddr) {
    asm volatile("ldmatrix.sync.aligned.m8n8.x4.shared.b16 {%0,%1,%2,%3}, [%4];"
        : "=r"(r0), "=r"(r1), "=r"(r2), "=r"(r3) : "r"(saddr));
}

__device__ __forceinline__ unsigned packh2(float lo, float hi) {
    __half2 h = __floats2half2_rn(lo, hi);
    return *(unsigned*)&h;
}

#define LDM_A_ROW(lane) ((((lane) >> 3) & 1) * 8 + ((lane) & 7))
#define LDM_A_K(lane)   ((((lane) >> 4) & 1) * 8)
#define LDM_B_ROW(lane) ((((lane) >> 4) & 1) * 8 + ((lane) & 7))
#define LDM_B_K(lane)   ((((lane) >> 3) & 1) * 8)

// ---------------------------------------------------------------------------
// Kernel P2: W -> W^T [n=256][k=1024] fp16
// ---------------------------------------------------------------------------
__global__ void prep_w_kernel(const float* __restrict__ Wk, const float* __restrict__ Wv) {
    const int n = blockIdx.x;
    const float* W = (n < KSZ) ? Wk : Wv;
    const int nc = (n < KSZ) ? n : (n - KSZ);
    for (int k = threadIdx.x; k < DIMS; k += blockDim.x)
        g_wth[(size_t)n * DIMS + k] = __float2half_rn(W[(size_t)k * KSZ + nc]);
}

// ---------------------------------------------------------------------------
// Kernel G: fused KV projection GEMM + X->out copy + X fp16 conversion.
// BM=128, BN=256, BK=64, 512 threads (16 warps 4m x 4n, warp tile 32x64).
// A: LDG fp32 -> cvt -> STS (software pipelined; same regs STG'd to out).
// B: cp.async double-buffered from g_wth.
// n 0..127 -> keys [tok][dim]; n 128..255 -> vals transposed [b][dim][tok].
// ---------------------------------------------------------------------------
#define GBK 64
#define ALD 72
#define BLD 72
#define GA_H (128 * ALD)                          // 9216
#define GB_H (256 * BLD)                          // 18432
#define GB_OFF (GA_H * 2)
#define GBUF_BYTES ((GA_H + GB_H) * 2)            // 55296
#define GEMM_SMEM_BYTES (2 * GBUF_BYTES)          // 110592

__global__ __launch_bounds__(512, 1) void kv_gemm_f16(
        const float* __restrict__ X, float* __restrict__ out,
        const float* __restrict__ bk, const float* __restrict__ bv) {
    extern __shared__ char smc[];
    const unsigned sbase = (unsigned)__cvta_generic_to_shared(smc);
    const int tid = threadIdx.x, lane = tid & 31, wid = tid >> 5;
    const int g = lane >> 2, t = lane & 3;
    const int wm = wid & 3, wn = wid >> 2;        // 4 x 4 warps
    const int m0 = blockIdx.x * 128;

    const int raA = LDM_A_ROW(lane), kaA = LDM_A_K(lane);
    const int rbB = LDM_B_ROW(lane), kbB = LDM_B_K(lane);

    // A chunk coords: 2 chunks/thread (i=0: rows 0-63, i=1: rows 64-127)
    const int ar0 = tid >> 3, ach = (tid & 7) * 8;

    float4 rA[2][2];   // [i][half of 8 floats]

    #define LDA(k0) do {                                                      \
        _Pragma("unroll")                                                     \
        for (int i = 0; i < 2; i++) {                                         \
            const float* p = X + (size_t)(m0 + ar0 + i * 64) * DIMS + (k0) + ach; \
            rA[i][0] = *(const float4*)p;                                     \
            rA[i][1] = *(const float4*)(p + 4);                               \
        }                                                                     \
    } while (0)

    #define STSA(bb) do {                                                     \
        unsigned ab = sbase + (bb) * GBUF_BYTES;                              \
        _Pragma("unroll")                                                     \
        for (int i = 0; i < 2; i++) {                                         \
            uint4 h;                                                          \
            h.x = packh2(rA[i][0].x, rA[i][0].y);                             \
            h.y = packh2(rA[i][0].z, rA[i][0].w);                             \
            h.z = packh2(rA[i][1].x, rA[i][1].y);                             \
            h.w = packh2(rA[i][1].z, rA[i][1].w);                             \
            asm volatile("st.shared.v4.b32 [%0], {%1,%2,%3,%4};"              \
                :: "r"(ab + ((ar0 + i * 64) * ALD + ach) * 2),                \
                   "r"(h.x), "r"(h.y), "r"(h.z), "r"(h.w));                   \
        }                                                                     \
    } while (0)

    #define STGA(k0) do {                                                     \
        _Pragma("unroll")                                                     \
        for (int i = 0; i < 2; i++) {                                         \
            float* p = out + (size_t)(m0 + ar0 + i * 64) * OUTD + (k0) + ach; \
            *(float4*)p = rA[i][0];                                           \
            *(float4*)(p + 4) = rA[i][1];                                     \
        }                                                                     \
    } while (0)

    #define G_LOAD_B(bb, k0) do {                                             \
        unsigned ab = sbase + (bb) * GBUF_BYTES + GB_OFF;                     \
        _Pragma("unroll")                                                     \
        for (int i = 0; i < 4; i++) {                                         \
            int idx = tid + i * 512;                                          \
            int row = idx >> 3, ch = idx & 7;                                 \
            cp16a(ab + (row * BLD + ch * 8) * 2,                              \
                  g_wth + (size_t)row * DIMS + (k0) + ch * 8);                \
        }                                                                     \
    } while (0)

    float acc[2][8][4];
    #pragma unroll
    for (int mt = 0; mt < 2; mt++)
        #pragma unroll
        for (int nt = 0; nt < 8; nt++)
            #pragma unroll
            for (int i = 0; i < 4; i++) acc[mt][nt][i] = 0.f;

    // prologue: A(0) ldg+sts+stg, B(0) cp.async
    LDA(0);
    STSA(0);
    STGA(0);
    G_LOAD_B(0, 0);
    CP_COMMIT();

    const int NK = DIMS / GBK;   // 16
    for (int kk0 = 0; kk0 < NK; kk0++) {
        if (kk0 + 1 < NK) {
            G_LOAD_B((kk0 + 1) & 1, (kk0 + 1) * GBK);
            CP_COMMIT();
            CP_WAIT(1);
        } else {
            CP_WAIT(0);
        }
        __syncthreads();   // A(kk0), B(kk0) visible

        // prefetch A(kk0+1) into regs (LDG latency overlaps compute below)
        if (kk0 + 1 < NK) LDA((kk0 + 1) * GBK);

        const unsigned ab = sbase + (kk0 & 1) * GBUF_BYTES;
        const unsigned aW = ab + ((wm * 32 + raA) * ALD + kaA) * 2;
        const unsigned bW = ab + GB_OFF + ((wn * 64 + rbB) * BLD + kbB) * 2;
        #pragma unroll
        for (int ks = 0; ks < 4; ks++) {
            const int kk = ks * 16;
            unsigned a[2][4];
            #pragma unroll
            for (int mt = 0; mt < 2; mt++)
                ldmat_x4(a[mt][0], a[mt][1], a[mt][2], a[mt][3],
                         aW + (mt * 16 * ALD + kk) * 2);
            #pragma unroll
            for (int ntp = 0; ntp < 4; ntp++) {
                unsigned b0a, b1a, b0b, b1b;
                ldmat_x4(b0a, b1a, b0b, b1b, bW + (ntp * 16 * BLD + kk) * 2);
                #pragma unroll
                for (int mt = 0; mt < 2; mt++) {
                    mma_f16(acc[mt][2 * ntp],
                            a[mt][0], a[mt][1], a[mt][2], a[mt][3], b0a, b1a);
                    mma_f16(acc[mt][2 * ntp + 1],
                            a[mt][0], a[mt][1], a[mt][2], a[mt][3], b0b, b1b);
                }
            }
        }
        __syncthreads();   // reads of buf[kk0&1] done

        if (kk0 + 1 < NK) {
            STSA((kk0 + 1) & 1);      // safe: that buffer last read at iter kk0-1
            STGA((kk0 + 1) * GBK);    // free X->out copy
        }
    }

    if (wn < 2) {
        // keys: fp16 [tok][dim]
        #pragma unroll
        for (int mt = 0; mt < 2; mt++) {
            int row = m0 + wm * 32 + mt * 16 + g;
            #pragma unroll
            for (int nt = 0; nt < 8; nt++) {
                int col = wn * 64 + nt * 8 + 2 * t;
                float b0 = bk[col], b1 = bk[col + 1];
                *(unsigned*)&g_keys_h[(size_t)row * KSZ + col] =
                    packh2(acc[mt][nt][0] + b0, acc[mt][nt][1] + b1);
                *(unsigned*)&g_keys_h[(size_t)(row + 8) * KSZ + col] =
                    packh2(acc[mt][nt][2] + b0, acc[mt][nt][3] + b1);
            }
        }
        __syncthreads();   // match vals warps
    } else {
        // vals: transpose via smem -> fp16 [b][dim][tok]
        __half* Vst = (__half*)smc;   // [dim 128][tok 128+8]
        #pragma unroll
        for (int mt = 0; mt < 2; mt++) {
            int r = wm * 32 + mt * 16 + g;
            #pragma unroll
            for (int nt = 0; nt < 8; nt++) {
                int dcol = (wn - 2) * 64 + nt * 8 + 2 * t;
                float b0 = bv[dcol], b1 = bv[dcol + 1];
                Vst[(dcol    ) * 136 + r    ] = __float2half_rn(acc[mt][nt][0] + b0);
                Vst[(dcol + 1) * 136 + r    ] = __float2half_rn(acc[mt][nt][1] + b1);
                Vst[(dcol    ) * 136 + r + 8] = __float2half_rn(acc[mt][nt][2] + b0);
                Vst[(dcol + 1) * 136 + r + 8] = __float2half_rn(acc[mt][nt][3] + b1);
            }
        }
        __syncthreads();
    }
    // cooperative global write of vals^T (all 512 threads)
    {
        __half* Vst = (__half*)smc;
        const int bb = m0 >> 11;
        const int tloc = m0 & 2047;
        #pragma unroll
        for (int i = 0; i < 4; i++) {
            int idx = tid + i * 512;      // 128 dims x 16 chunks
            int col = idx >> 4, ch = idx & 15;
            uint4 v = *(uint4*)&Vst[col * 136 + ch * 8];
            *(uint4*)&g_valsT_h[((size_t)bb * KSZ + col) * SEQ + tloc + ch * 8] = v;
        }
    }
}

// ---------------------------------------------------------------------------
// Kernel A: causal flash attention, fp16 mma + ldmatrix, dual warp-group.
// (unchanged from R10)
// ---------------------------------------------------------------------------
#define AQ 64
#define AK 64
#define KLD 136
#define VLD 72
#define PLD 72
#define NQT (SEQ / AQ)               // 32
#define K_TILE_H (AK * KLD)          // 8704
#define VT_TILE_H (KSZ * VLD)        // 9216
#define GOFF_K0 0
#define GOFF_K1 (K_TILE_H)
#define GOFF_VT0 (2 * K_TILE_H)
#define GOFF_VT1 (2 * K_TILE_H + VT_TILE_H)
#define GOFF_P  (2 * K_TILE_H + 2 * VT_TILE_H)
#define GRP_H (GOFF_P + AQ * PLD)
#define ATTN_SMEM_BYTES (2 * GRP_H * 2)             // 161792

__global__ __launch_bounds__(256, 1) void attn_kernel(float* __restrict__ out) {
    extern __shared__ char smc[];
    const int tid = threadIdx.x, lane = tid & 31, wid = tid >> 5;
    const int g = lane >> 2, t = lane & 3;
    const int grp = wid >> 2, wg = wid & 3, gt = tid & 127;
    const int barid = grp + 1;
    #define GBAR() asm volatile("bar.sync %0, 128;" :: "r"(barid))

    char* gbase = smc + grp * GRP_H * 2;
    const unsigned sgb = (unsigned)__cvta_generic_to_shared(gbase);

    const int pairIdx = blockIdx.x;
    const int bq = blockIdx.y;
    const int qt = grp ? (NQT - 1 - pairIdx) : pairIdx;
    const int qbase = qt * AQ;
    const int nkt = qt + 1;
    const __half* keys = g_keys_h + (size_t)bq * SEQ * KSZ;
    const __half* valsT = g_valsT_h + (size_t)bq * KSZ * SEQ;
    const float scale = 0.08838834764831843f;   // 1/sqrt(128)

    const int raA = LDM_A_ROW(lane), kaA = LDM_A_K(lane);
    const int rbB = LDM_B_ROW(lane), kbB = LDM_B_K(lane);
    const int rw = wg * 16;

    #define LOAD_KV(buf, kbase) do {                                          \
        _Pragma("unroll")                                                     \
        for (int i = 0; i < 8; i++) {                                         \
            int idx = gt + i * 128;                                           \
            int row = idx >> 4, ch = idx & 15;                                \
            cp16a(sgb + ((buf ? GOFF_K1 : GOFF_K0) + row * KLD + ch * 8) * 2, \
                  keys + (size_t)((kbase) + row) * KSZ + ch * 8);             \
        }                                                                     \
        _Pragma("unroll")                                                     \
        for (int i = 0; i < 8; i++) {                                         \
            int idx = gt + i * 128;                                           \
            int row = idx >> 3, ch = idx & 7;                                 \
            cp16a(sgb + ((buf ? GOFF_VT1 : GOFF_VT0) + row * VLD + ch * 8) * 2, \
                  valsT + (size_t)row * SEQ + (kbase) + ch * 8);              \
        }                                                                     \
    } while (0)

    // stage Q through K0 region
    #pragma unroll
    for (int i = 0; i < 8; i++) {
        int idx = gt + i * 128;
        int row = idx >> 4, ch = idx & 15;
        cp16a(sgb + (row * KLD + ch * 8) * 2,
              keys + (size_t)(qbase + row) * KSZ + ch * 8);
    }
    CP_COMMIT();
    CP_WAIT(0);
    GBAR();

    // Q fragments via ldmatrix (a-type)
    unsigned qa[8][4];
    {
        const unsigned qW = sgb + ((rw + raA) * KLD + kaA) * 2;
        #pragma unroll
        for (int ks = 0; ks < 8; ks++)
            ldmat_x4(qa[ks][0], qa[ks][1], qa[ks][2], qa[ks][3], qW + ks * 32);
    }
    GBAR();

    LOAD_KV(0, 0);
    CP_COMMIT();

    float O[16][4];
    #pragma unroll
    for (int nt = 0; nt < 16; nt++)
        #pragma unroll
        for (int i = 0; i < 4; i++) O[nt][i] = 0.f;
    float mrow[2] = {-1e30f, -1e30f};
    float lrow[2] = {0.f, 0.f};

    for (int j = 0; j < nkt; j++) {
        if (j + 1 < nkt) {
            LOAD_KV((j + 1) & 1, (j + 1) * AK);
            CP_COMMIT();
            CP_WAIT(1);
        } else {
            CP_WAIT(0);
        }
        GBAR();

        const unsigned kW = sgb + ((j & 1) ? GOFF_K1 : GOFF_K0) * 2
                          + (rbB * KLD + kbB) * 2;
        const unsigned vW = sgb + ((j & 1) ? GOFF_VT1 : GOFF_VT0) * 2
                          + (rbB * VLD + kbB) * 2;
        unsigned* Ps32 = (unsigned*)(gbase + GOFF_P * 2);
        const int kbase = j * AK;

        // S = Q @ K^T : 16 rows x 64 keys
        float s[8][4];
        #pragma unroll
        for (int nt = 0; nt < 8; nt++)
            #pragma unroll
            for (int i = 0; i < 4; i++) s[nt][i] = 0.f;

        #pragma unroll
        for (int ks = 0; ks < 8; ks++) {
            #pragma unroll
            for (int ntp = 0; ntp < 4; ntp++) {
                unsigned b0a, b1a, b0b, b1b;
                ldmat_x4(b0a, b1a, b0b, b1b, kW + (ntp * 16 * KLD + ks * 16) * 2);
                mma_f16(s[2 * ntp],
                        qa[ks][0], qa[ks][1], qa[ks][2], qa[ks][3], b0a, b1a);
                mma_f16(s[2 * ntp + 1],
                        qa[ks][0], qa[ks][1], qa[ks][2], qa[ks][3], b0b, b1b);
            }
        }

        #pragma unroll
        for (int nt = 0; nt < 8; nt++)
            #pragma unroll
            for (int i = 0; i < 4; i++) s[nt][i] *= scale;

        // causal mask on diagonal tile only, exactly -100
        if (j == nkt - 1) {
            const int qg0 = qbase + rw + g;
            const int qg1 = qg0 + 8;
            #pragma unroll
            for (int nt = 0; nt < 8; nt++) {
                int kg = kbase + nt * 8 + 2 * t;
                if (kg     > qg0) s[nt][0] = -100.0f;
                if (kg + 1 > qg0) s[nt][1] = -100.0f;
                if (kg     > qg1) s[nt][2] = -100.0f;
                if (kg + 1 > qg1) s[nt][3] = -100.0f;
            }
        }

        // online softmax; O-rescale only when the running max changes
        #pragma unroll
        for (int h = 0; h < 2; h++) {
            float mx = -1e30f;
            #pragma unroll
            for (int nt = 0; nt < 8; nt++)
                mx = fmaxf(mx, fmaxf(s[nt][2 * h], s[nt][2 * h + 1]));
            mx = fmaxf(mx, __shfl_xor_sync(0xffffffffu, mx, 1));
            mx = fmaxf(mx, __shfl_xor_sync(0xffffffffu, mx, 2));
            if (mx > mrow[h]) {
                float alpha = __expf(mrow[h] - mx);
                mrow[h] = mx;
                lrow[h] *= alpha;
                #pragma unroll
                for (int nt = 0; nt < 16; nt++) {
                    O[nt][2 * h]     *= alpha;
                    O[nt][2 * h + 1] *= alpha;
                }
            }
            float m = mrow[h];
            float sum = 0.f;
            #pragma unroll
            for (int nt = 0; nt < 8; nt++) {
                float p0 = __expf(s[nt][2 * h] - m);
                float p1 = __expf(s[nt][2 * h + 1] - m);
                s[nt][2 * h] = p0; s[nt][2 * h + 1] = p1;
                sum += p0 + p1;
            }
            sum += __shfl_xor_sync(0xffffffffu, sum, 1);
            sum += __shfl_xor_sync(0xffffffffu, sum, 2);
            lrow[h] += sum;
        }

        // stage P as fp16 pairs in per-warp smem rows
        {
            #pragma unroll
            for (int nt = 0; nt < 8; nt++) {
                int col = nt * 8 + 2 * t;
                Ps32[((rw + g) * PLD + col) >> 1]     = packh2(s[nt][0], s[nt][1]);
                Ps32[((rw + g + 8) * PLD + col) >> 1] = packh2(s[nt][2], s[nt][3]);
            }
        }
        __syncwarp();

        // O += P @ V
        const unsigned pW = sgb + GOFF_P * 2 + ((rw + raA) * PLD + kaA) * 2;
        #pragma unroll
        for (int ks = 0; ks < 4; ks++) {
            unsigned pa0, pa1, pa2, pa3;
            ldmat_x4(pa0, pa1, pa2, pa3, pW + ks * 32);
            #pragma unroll
            for (int ntp = 0; ntp < 8; ntp++) {
                unsigned b0a, b1a, b0b, b1b;
                ldmat_x4(b0a, b1a, b0b, b1b, vW + (ntp * 16 * VLD + ks * 16) * 2);
                mma_f16(O[2 * ntp], pa0, pa1, pa2, pa3, b0a, b1a);
                mma_f16(O[2 * ntp + 1], pa0, pa1, pa2, pa3, b0b, b1b);
            }
        }
        GBAR();
    }

    // epilogue: normalize, write out[:, 1024:1152]
    {
        float inv0 = 1.0f / lrow[0];
        float inv1 = 1.0f / lrow[1];
        int qg0 = qbase + rw + g;
        size_t base0 = ((size_t)bq * SEQ + qg0) * OUTD + DIMS;
        size_t base1 = base0 + (size_t)8 * OUTD;
        #pragma unroll
        for (int nt = 0; nt < 16; nt++) {
            int c = nt * 8 + 2 * t;
            *(float2*)(out + base0 + c) = make_float2(O[nt][0] * inv0, O[nt][1] * inv0);
            *(float2*)(out + base1 + c) = make_float2(O[nt][2] * inv1, O[nt][3] * inv1);
        }
    }
}

// ---------------------------------------------------------------------------
extern "C" void kernel_launch(void* const* d_in, const int* in_sizes, int n_in,
                              void* d_out, int out_size) {
    const float* X  = (const float*)d_in[0];
    const float* Wk = (const float*)d_in[1];
    const float* bk = (const float*)d_in[2];
    const float* Wv = (const float*)d_in[3];
    const float* bv = (const float*)d_in[4];
    float* out = (float*)d_out;

    prep_w_kernel<<<2 * KSZ, 256>>>(Wk, Wv);

    cudaFuncSetAttribute(kv_gemm_f16, cudaFuncAttributeMaxDynamicSharedMemorySize,
                         GEMM_SMEM_BYTES);
    kv_gemm_f16<<<M_TOTAL / 128, 512, GEMM_SMEM_BYTES>>>(X, out, bk, bv);

    cudaFuncSetAttribute(attn_kernel, cudaFuncAttributeMaxDynamicSharedMemorySize,
                         ATTN_SMEM_BYTES);
    attn_kernel<<<dim3(NQT / 2, BATCH), 256, ATTN_SMEM_BYTES>>>(out);
}